// round 1
// baseline (speedup 1.0000x reference)
#include <cuda_runtime.h>
#include <math.h>

#define B_   1024
#define L_   32
#define K_   8
#define G_   8
#define C_   128
#define S_   32
#define DIN_ 104
#define BPL  9          // blocks per latent
#define NCHUNK 256      // (B*G)/32 row-chunks per latent

// scratch (module-level, allocation-free)
__device__ unsigned char g_ci[B_ * L_];
__device__ float g_ep[K_ * K_];

// packed dual-FMA: ptxas only emits FFMA2 from PTX fma.rn.f32x2
__device__ __forceinline__ float2 ffma2(float2 a, float2 b, float2 c) {
    union U { float2 f; unsigned long long u; };
    U A, Bv, Cv, D;
    A.f = a; Bv.f = b; Cv.f = c;
    asm("fma.rn.f32x2 %0, %1, %2, %3;" : "=l"(D.u) : "l"(A.u), "l"(Bv.u), "l"(Cv.u));
    return D.f;
}

__global__ void prep_kernel(const float* __restrict__ tp,   // target_params [L,K]
                            const float* __restrict__ ug,   // u_gumbel [B,L,K]
                            const float* __restrict__ th,   // enco_theta [K,K]
                            const float* __restrict__ ga,   // enco_gamma [K,K]
                            float* __restrict__ out) {
    int b = blockIdx.x, l = threadIdx.x;
    const float* u = ug + (b * L_ + l) * K_;
    float best = -1e30f; int bi = 0;
#pragma unroll
    for (int k = 0; k < K_; k++) {
        float gum = -logf(-logf(u[k] + 1e-10f) + 1e-10f);
        float v = tp[l * K_ + k] + gum;
        if (v > best) { best = v; bi = k; }
    }
    g_ci[b * L_ + l] = (unsigned char)bi;
    if (l == 0) out[b] = 0.0f;
    if (b == 0) {
        for (int e = l; e < K_ * K_; e += L_) {
            float s1 = 1.0f / (1.0f + expf(-th[e]));
            float s2 = 1.0f / (1.0f + expf(-ga[e]));
            g_ep[e] = s1 * s2;
        }
    }
}

// SMEM layout (floats):
// W1s  [104][128] -> 13312
// W2s  [128][128] -> 16384
// W3s  [2][128]   -> 256
// b1,g1w,g1b,b2,g2w,g2b -> 6*128 = 768
// eps  [64], bts [4]
// buf: 8 warps * 4 rows * 132 float2
#define SMEM_FLOATS (30788 + 4224 * 2)
#define SMEM_BYTES  (SMEM_FLOATS * 4)

__global__ __launch_bounds__(256, 1) void main_kernel(
    const float* __restrict__ z_sample, const int* __restrict__ target,
    const float* __restrict__ z_mean,   const float* __restrict__ z_logstd,
    const float* __restrict__ z_shared, const float* __restrict__ u_adj,
    const float* __restrict__ W1, const float* __restrict__ b1g,
    const float* __restrict__ g1wg, const float* __restrict__ g1bg,
    const float* __restrict__ W2, const float* __restrict__ b2g,
    const float* __restrict__ g2wg, const float* __restrict__ g2bg,
    const float* __restrict__ W3, const float* __restrict__ b3g,
    const float* __restrict__ tsc, float* __restrict__ out)
{
    extern __shared__ float sm[];
    float* W1s  = sm;            // 13312
    float* W2s  = sm + 13312;    // 16384
    float* W3s  = sm + 29696;    // 256
    float* sb1  = sm + 29952;
    float* sg1w = sm + 30080;
    float* sg1b = sm + 30208;
    float* sb2  = sm + 30336;
    float* sg2w = sm + 30464;
    float* sg2b = sm + 30592;
    float* seps = sm + 30720;    // 64
    float* sbts = sm + 30784;    // 4
    float2* buf = (float2*)(sm + 30788);

    const int tid = threadIdx.x;
    const int l = blockIdx.x / BPL;
    const int t = blockIdx.x % BPL;

    // transposed weight copies: smem [d][c], coalesced STS (global reads are L2-hot)
    const float* W1g = W1 + l * C_ * DIN_;
    for (int idx = tid; idx < C_ * DIN_; idx += 256) {
        int d = idx >> 7, c = idx & 127;
        W1s[idx] = W1g[c * DIN_ + d];
    }
    const float* W2g = W2 + l * C_ * C_;
    for (int idx = tid; idx < C_ * C_; idx += 256) {
        int d = idx >> 7, c = idx & 127;
        W2s[idx] = W2g[c * C_ + d];
    }
    for (int idx = tid; idx < 2 * C_; idx += 256) W3s[idx] = W3[l * 2 * C_ + idx];
    if (tid < C_) {
        sb1[tid]  = b1g[l * C_ + tid];
        sg1w[tid] = g1wg[l * C_ + tid];
        sg1b[tid] = g1bg[l * C_ + tid];
        sb2[tid]  = b2g[l * C_ + tid];
        sg2w[tid] = g2wg[l * C_ + tid];
        sg2b[tid] = g2bg[l * C_ + tid];
    }
    if (tid < 64) seps[tid] = g_ep[tid];
    if (tid < 2) sbts[tid] = b3g[l * 2 + tid];
    else if (tid < 4) sbts[tid] = tsc[l * 2 + tid - 2];
    __syncthreads();

    const int w = tid >> 5, lane = tid & 31;
    float2* mybuf = buf + w * 4 * 132;

    const float4 bias1 = *(const float4*)&sb1[lane * 4];
    const float4 gw1   = *(const float4*)&sg1w[lane * 4];
    const float4 gb1   = *(const float4*)&sg1b[lane * 4];
    const float4 bias2 = *(const float4*)&sb2[lane * 4];
    const float4 gw2   = *(const float4*)&sg2w[lane * 4];
    const float4 gb2   = *(const float4*)&sg2b[lane * 4];
    const float4 w30   = *(const float4*)&W3s[lane * 4];
    const float4 w31   = *(const float4*)&W3s[128 + lane * 4];
    const float b3_0 = sbts[0], b3_1 = sbts[1];
    const float sc0 = expf(sbts[2]), sc1 = expf(sbts[3]);
    const float isc0 = 1.0f / sc0, isc1 = 1.0f / sc1;

    for (int ch = t; ch < NCHUNK; ch += BPL) {
        const int rowbase = (ch << 5) + (w << 2);   // 4 rows share b (g in {0..3} or {4..7})
        const int b = rowbase >> 3;
        const int g0 = rowbase & 7;
        const int j = lane;

        const int cl  = g_ci[b * L_ + l];
        const int cj  = g_ci[b * L_ + j];
        const int tgt = target[b];
        const float zs  = z_sample[b * L_ + j];
        const float zsh = z_shared[b * S_ + j];
        const float epv = seps[cj * K_ + cl];
        const float notdiag = (j != l) ? 1.0f : 0.0f;
        const float tv = (j < 8) ? (((j == tgt) && (cl == tgt)) ? 1.0f : 0.0f) : 0.0f;
        const float zl  = z_logstd[b * L_ + l];
        const float zmn = z_mean[b * L_ + l];

        __syncwarp();
#pragma unroll
        for (int m = 0; m < 4; m++) {
            float u = u_adj[((b * G_ + g0 + m) * K_ + cj) * K_ + cl];
            float mk = (u < epv) ? notdiag : 0.0f;
            float zms = mk * zs;
            mybuf[m * 132 + j]      = make_float2(zms, zms);
            mybuf[m * 132 + 32 + j] = make_float2(mk, mk);
            if (j < 8) mybuf[m * 132 + 64 + j] = make_float2(tv, tv);
            mybuf[m * 132 + 72 + j] = make_float2(zsh, zsh);
        }
        __syncwarp();

        // ---------------- layer 1: [104] -> [128] ----------------
        float2 acc[4][2];
#pragma unroll
        for (int m = 0; m < 4; m++) { acc[m][0] = make_float2(0.f, 0.f); acc[m][1] = make_float2(0.f, 0.f); }

#pragma unroll 4
        for (int d = 0; d < DIN_; d++) {
            float4 w4 = *(const float4*)&W1s[d * C_ + lane * 4];
            float2 wlo = make_float2(w4.x, w4.y);
            float2 whi = make_float2(w4.z, w4.w);
#pragma unroll
            for (int m = 0; m < 4; m++) {
                float2 xv = mybuf[m * 132 + d];
                acc[m][0] = ffma2(wlo, xv, acc[m][0]);
                acc[m][1] = ffma2(whi, xv, acc[m][1]);
            }
        }
        __syncwarp();

#pragma unroll
        for (int m = 0; m < 4; m++) {
            float v0 = acc[m][0].x + bias1.x;
            float v1 = acc[m][0].y + bias1.y;
            float v2 = acc[m][1].x + bias1.z;
            float v3 = acc[m][1].y + bias1.w;
            float s  = v0 + v1 + v2 + v3;
            float ss = v0 * v0 + v1 * v1 + v2 * v2 + v3 * v3;
#pragma unroll
            for (int o = 16; o > 0; o >>= 1) {
                s  += __shfl_xor_sync(0xffffffffu, s,  o);
                ss += __shfl_xor_sync(0xffffffffu, ss, o);
            }
            float mu  = s * (1.0f / 128.0f);
            float var = ss * (1.0f / 128.0f) - mu * mu;
            float inv = rsqrtf(var + 1e-5f);
            float h0 = (v0 - mu) * inv * gw1.x + gb1.x; h0 = h0 / (1.0f + expf(-h0));
            float h1 = (v1 - mu) * inv * gw1.y + gb1.y; h1 = h1 / (1.0f + expf(-h1));
            float h2 = (v2 - mu) * inv * gw1.z + gb1.z; h2 = h2 / (1.0f + expf(-h2));
            float h3 = (v3 - mu) * inv * gw1.w + gb1.w; h3 = h3 / (1.0f + expf(-h3));
            mybuf[m * 132 + lane * 4 + 0] = make_float2(h0, h0);
            mybuf[m * 132 + lane * 4 + 1] = make_float2(h1, h1);
            mybuf[m * 132 + lane * 4 + 2] = make_float2(h2, h2);
            mybuf[m * 132 + lane * 4 + 3] = make_float2(h3, h3);
        }
        __syncwarp();

        // ---------------- layer 2: [128] -> [128] ----------------
#pragma unroll
        for (int m = 0; m < 4; m++) { acc[m][0] = make_float2(0.f, 0.f); acc[m][1] = make_float2(0.f, 0.f); }

#pragma unroll 4
        for (int d = 0; d < C_; d++) {
            float4 w4 = *(const float4*)&W2s[d * C_ + lane * 4];
            float2 wlo = make_float2(w4.x, w4.y);
            float2 whi = make_float2(w4.z, w4.w);
#pragma unroll
            for (int m = 0; m < 4; m++) {
                float2 xv = mybuf[m * 132 + d];
                acc[m][0] = ffma2(wlo, xv, acc[m][0]);
                acc[m][1] = ffma2(whi, xv, acc[m][1]);
            }
        }

        // ---------------- GN2 + SiLU + layer 3 + KL ----------------
        float kacc = 0.0f;
#pragma unroll
        for (int m = 0; m < 4; m++) {
            float v0 = acc[m][0].x + bias2.x;
            float v1 = acc[m][0].y + bias2.y;
            float v2 = acc[m][1].x + bias2.z;
            float v3 = acc[m][1].y + bias2.w;
            float s  = v0 + v1 + v2 + v3;
            float ss = v0 * v0 + v1 * v1 + v2 * v2 + v3 * v3;
#pragma unroll
            for (int o = 16; o > 0; o >>= 1) {
                s  += __shfl_xor_sync(0xffffffffu, s,  o);
                ss += __shfl_xor_sync(0xffffffffu, ss, o);
            }
            float mu  = s * (1.0f / 128.0f);
            float var = ss * (1.0f / 128.0f) - mu * mu;
            float inv = rsqrtf(var + 1e-5f);
            float h0 = (v0 - mu) * inv * gw2.x + gb2.x; h0 = h0 / (1.0f + expf(-h0));
            float h1 = (v1 - mu) * inv * gw2.y + gb2.y; h1 = h1 / (1.0f + expf(-h1));
            float h2 = (v2 - mu) * inv * gw2.z + gb2.z; h2 = h2 / (1.0f + expf(-h2));
            float h3 = (v3 - mu) * inv * gw2.w + gb2.w; h3 = h3 / (1.0f + expf(-h3));

            float p0 = h0 * w30.x + h1 * w30.y + h2 * w30.z + h3 * w30.w;
            float p1 = h0 * w31.x + h1 * w31.y + h2 * w31.z + h3 * w31.w;
#pragma unroll
            for (int o = 16; o > 0; o >>= 1) {
                p0 += __shfl_xor_sync(0xffffffffu, p0, o);
                p1 += __shfl_xor_sync(0xffffffffu, p1, o);
            }
            if (lane == 0) {
                float o0 = p0 + b3_0, o1 = p1 + b3_1;
                float pm = tanhf(o0 * isc0) * sc0;
                float pl = tanhf(o1 * isc1) * sc1;
                float dmu = zmn - pm;
                kacc += pl - zl + (expf(2.0f * zl) + dmu * dmu) * 0.5f * expf(-2.0f * pl) - 0.5f;
            }
        }
        if (lane == 0) atomicAdd(out + b, kacc * 0.125f);
    }
}

extern "C" void kernel_launch(void* const* d_in, const int* in_sizes, int n_in,
                              void* d_out, int out_size) {
    const float* z_sample      = (const float*)d_in[0];
    const int*   target        = (const int*)  d_in[1];
    const float* z_mean        = (const float*)d_in[2];
    const float* z_logstd      = (const float*)d_in[3];
    const float* z_shared      = (const float*)d_in[4];
    const float* u_gumbel      = (const float*)d_in[5];
    const float* u_adj         = (const float*)d_in[6];
    const float* target_params = (const float*)d_in[7];
    const float* enco_theta    = (const float*)d_in[8];
    const float* enco_gamma    = (const float*)d_in[9];
    const float* W1            = (const float*)d_in[10];
    const float* b1            = (const float*)d_in[11];
    const float* gn1_w         = (const float*)d_in[12];
    const float* gn1_b         = (const float*)d_in[13];
    const float* W2            = (const float*)d_in[14];
    const float* b2            = (const float*)d_in[15];
    const float* gn2_w         = (const float*)d_in[16];
    const float* gn2_b         = (const float*)d_in[17];
    const float* W3            = (const float*)d_in[18];
    const float* b3            = (const float*)d_in[19];
    const float* tanh_scale    = (const float*)d_in[20];
    float* out = (float*)d_out;

    prep_kernel<<<B_, L_>>>(target_params, u_gumbel, enco_theta, enco_gamma, out);

    cudaFuncSetAttribute(main_kernel, cudaFuncAttributeMaxDynamicSharedMemorySize, SMEM_BYTES);
    main_kernel<<<L_ * BPL, 256, SMEM_BYTES>>>(
        z_sample, target, z_mean, z_logstd, z_shared, u_adj,
        W1, b1, gn1_w, gn1_b, W2, b2, gn2_w, gn2_b, W3, b3, tanh_scale, out);
}

// round 2
// speedup vs baseline: 1.4399x; 1.4399x over previous
#include <cuda_runtime.h>
#include <math.h>

#define B_   1024
#define L_   32
#define K_   8
#define G_   8
#define C_   128
#define S_   32
#define DIN_ 104
#define GRID_MAIN 152
#define NITEMS (L_ * 128)      // 32 latents x 128 chunks (chunk = 64 rows = 8 warps x 8 rows)

// scratch (module-level, allocation-free)
__device__ unsigned char g_ci[B_ * L_];
__device__ float g_ep[K_ * K_];

// packed dual-FMA: ptxas only emits FFMA2 from PTX fma.rn.f32x2
__device__ __forceinline__ float2 ffma2(float2 a, float2 b, float2 c) {
    union U { float2 f; unsigned long long u; };
    U A, Bv, Cv, D;
    A.f = a; Bv.f = b; Cv.f = c;
    asm("fma.rn.f32x2 %0, %1, %2, %3;" : "=l"(D.u) : "l"(A.u), "l"(Bv.u), "l"(Cv.u));
    return D.f;
}

__device__ __forceinline__ float silu_f(float x) {
    return x * (1.0f / (1.0f + __expf(-x)));
}

__global__ void prep_kernel(const float* __restrict__ tp,   // target_params [L,K]
                            const float* __restrict__ ug,   // u_gumbel [B,L,K]
                            const float* __restrict__ th,   // enco_theta [K,K]
                            const float* __restrict__ ga,   // enco_gamma [K,K]
                            float* __restrict__ out) {
    int b = blockIdx.x, l = threadIdx.x;
    const float* u = ug + (b * L_ + l) * K_;
    float best = -1e30f; int bi = 0;
#pragma unroll
    for (int k = 0; k < K_; k++) {
        float gum = -logf(-logf(u[k] + 1e-10f) + 1e-10f);
        float v = tp[l * K_ + k] + gum;
        if (v > best) { best = v; bi = k; }
    }
    g_ci[b * L_ + l] = (unsigned char)bi;
    if (l == 0) out[b] = 0.0f;
    if (b == 0) {
        for (int e = l; e < K_ * K_; e += L_) {
            float s1 = 1.0f / (1.0f + expf(-th[e]));
            float s2 = 1.0f / (1.0f + expf(-ga[e]));
            g_ep[e] = s1 * s2;
        }
    }
}

// SMEM layout (floats):
// W1s [104][128] = 13312 | W2s [128][128] = 16384 | W3s [2][128] = 256
// b1,g1w,g1b,b2,g2w,g2b = 768 | eps 64 | bts 4  -> 30788
// buf: 8 warps * 8 rows * 128 floats = 8192
#define SMEM_FLOATS (30788 + 8192)
#define SMEM_BYTES  (SMEM_FLOATS * 4)

__global__ __launch_bounds__(256, 1) void main_kernel(
    const float* __restrict__ z_sample, const int* __restrict__ target,
    const float* __restrict__ z_mean,   const float* __restrict__ z_logstd,
    const float* __restrict__ z_shared, const float* __restrict__ u_adj,
    const float* __restrict__ W1, const float* __restrict__ b1g,
    const float* __restrict__ g1wg, const float* __restrict__ g1bg,
    const float* __restrict__ W2, const float* __restrict__ b2g,
    const float* __restrict__ g2wg, const float* __restrict__ g2bg,
    const float* __restrict__ W3, const float* __restrict__ b3g,
    const float* __restrict__ tsc, float* __restrict__ out)
{
    extern __shared__ float sm[];
    float* W1s  = sm;            // 13312
    float* W2s  = sm + 13312;    // 16384
    float* W3s  = sm + 29696;    // 256
    float* sb1  = sm + 29952;
    float* sg1w = sm + 30080;
    float* sg1b = sm + 30208;
    float* sb2  = sm + 30336;
    float* sg2w = sm + 30464;
    float* sg2b = sm + 30592;
    float* seps = sm + 30720;    // 64
    float* sbts = sm + 30784;    // 4
    float* buf  = sm + 30788;    // 8 warps * 1024

    const int tid = threadIdx.x;
    const int w = tid >> 5, lane = tid & 31;
    float* mybuf = buf + w * 1024;

    const int start = (int)(((long long)blockIdx.x * NITEMS) / gridDim.x);
    const int end   = (int)(((long long)(blockIdx.x + 1) * NITEMS) / gridDim.x);

    int cur_l = -1;
    float4 bias1, gw1, gb1, bias2, gw2, gb2, w30, w31;
    float b3_0 = 0.f, b3_1 = 0.f, sc0 = 1.f, sc1 = 1.f, isc0 = 1.f, isc1 = 1.f;

    for (int item = start; item < end; item++) {
        const int l = item >> 7;
        const int ch = item & 127;

        if (l != cur_l) {
            __syncthreads();
            // transposed weight copies: smem [d][c]
            const float* W1g = W1 + l * C_ * DIN_;
            for (int idx = tid; idx < C_ * DIN_; idx += 256) {
                int d = idx >> 7, c = idx & 127;
                W1s[idx] = W1g[c * DIN_ + d];
            }
            const float* W2g = W2 + l * C_ * C_;
            for (int idx = tid; idx < C_ * C_; idx += 256) {
                int d = idx >> 7, c = idx & 127;
                W2s[idx] = W2g[c * C_ + d];
            }
            for (int idx = tid; idx < 2 * C_; idx += 256) W3s[idx] = W3[l * 2 * C_ + idx];
            if (tid < C_) {
                sb1[tid]  = b1g[l * C_ + tid];
                sg1w[tid] = g1wg[l * C_ + tid];
                sg1b[tid] = g1bg[l * C_ + tid];
                sb2[tid]  = b2g[l * C_ + tid];
                sg2w[tid] = g2wg[l * C_ + tid];
                sg2b[tid] = g2bg[l * C_ + tid];
            }
            if (tid < 64) seps[tid] = g_ep[tid];
            if (tid < 2) sbts[tid] = b3g[l * 2 + tid];
            else if (tid < 4) sbts[tid] = tsc[l * 2 + tid - 2];
            __syncthreads();

            bias1 = *(const float4*)&sb1[lane * 4];
            gw1   = *(const float4*)&sg1w[lane * 4];
            gb1   = *(const float4*)&sg1b[lane * 4];
            bias2 = *(const float4*)&sb2[lane * 4];
            gw2   = *(const float4*)&sg2w[lane * 4];
            gb2   = *(const float4*)&sg2b[lane * 4];
            w30   = *(const float4*)&W3s[lane * 4];
            w31   = *(const float4*)&W3s[128 + lane * 4];
            b3_0 = sbts[0]; b3_1 = sbts[1];
            sc0 = __expf(sbts[2]); sc1 = __expf(sbts[3]);
            isc0 = 1.0f / sc0; isc1 = 1.0f / sc1;
            cur_l = l;
        }

        const int b = ch * 8 + w;                 // one batch element, all 8 graphs
        const int cl  = g_ci[b * L_ + l];
        const int cj  = g_ci[b * L_ + lane];
        const int tgt = target[b];
        const float zs  = z_sample[b * L_ + lane];
        const float zsh = z_shared[b * S_ + lane];
        const float epv = seps[cj * K_ + cl];
        const float notdiag = (lane != l) ? 1.0f : 0.0f;
        const float tv = (lane < 8) ? (((lane == tgt) && (cl == tgt)) ? 1.0f : 0.0f) : 0.0f;
        const float zl  = z_logstd[b * L_ + l];
        const float zmn = z_mean[b * L_ + l];

        __syncwarp();
#pragma unroll
        for (int m = 0; m < 8; m++) {
            float u = u_adj[((b * G_ + m) * K_ + cj) * K_ + cl];
            float mk = (u < epv) ? notdiag : 0.0f;
            mybuf[m * 128 + lane]      = mk * zs;
            mybuf[m * 128 + 32 + lane] = mk;
            if (lane < 8) mybuf[m * 128 + 64 + lane] = tv;
            mybuf[m * 128 + 72 + lane] = zsh;
        }
        __syncwarp();

        const float4* xb = (const float4*)mybuf;   // row m at xb + m*32

        // ---------------- layer 1: [104] -> [128] ----------------
        float2 acc[8][2];
#pragma unroll
        for (int m = 0; m < 8; m++) { acc[m][0] = make_float2(0.f, 0.f); acc[m][1] = make_float2(0.f, 0.f); }

#pragma unroll 2
        for (int d4 = 0; d4 < DIN_ / 4; d4++) {
            float4 xr[8];
#pragma unroll
            for (int m = 0; m < 8; m++) xr[m] = xb[m * 32 + d4];
#pragma unroll
            for (int q = 0; q < 4; q++) {
                float4 w4 = *(const float4*)&W1s[(d4 * 4 + q) * C_ + lane * 4];
                float2 wlo = make_float2(w4.x, w4.y);
                float2 whi = make_float2(w4.z, w4.w);
#pragma unroll
                for (int m = 0; m < 8; m++) {
                    float xv = (q == 0) ? xr[m].x : (q == 1) ? xr[m].y : (q == 2) ? xr[m].z : xr[m].w;
                    float2 xx = make_float2(xv, xv);
                    acc[m][0] = ffma2(wlo, xx, acc[m][0]);
                    acc[m][1] = ffma2(whi, xx, acc[m][1]);
                }
            }
        }
        __syncwarp();

        // ---------------- GN1 + SiLU ----------------
#pragma unroll
        for (int m = 0; m < 8; m++) {
            float v0 = acc[m][0].x + bias1.x;
            float v1 = acc[m][0].y + bias1.y;
            float v2 = acc[m][1].x + bias1.z;
            float v3 = acc[m][1].y + bias1.w;
            float s  = v0 + v1 + v2 + v3;
            float ss = v0 * v0 + v1 * v1 + v2 * v2 + v3 * v3;
#pragma unroll
            for (int o = 16; o > 0; o >>= 1) {
                s  += __shfl_xor_sync(0xffffffffu, s,  o);
                ss += __shfl_xor_sync(0xffffffffu, ss, o);
            }
            float mu  = s * (1.0f / 128.0f);
            float var = ss * (1.0f / 128.0f) - mu * mu;
            float inv = rsqrtf(var + 1e-5f);
            float h0 = silu_f((v0 - mu) * inv * gw1.x + gb1.x);
            float h1 = silu_f((v1 - mu) * inv * gw1.y + gb1.y);
            float h2 = silu_f((v2 - mu) * inv * gw1.z + gb1.z);
            float h3 = silu_f((v3 - mu) * inv * gw1.w + gb1.w);
            *(float4*)&mybuf[m * 128 + lane * 4] = make_float4(h0, h1, h2, h3);
        }
        __syncwarp();

        // ---------------- layer 2: [128] -> [128] ----------------
#pragma unroll
        for (int m = 0; m < 8; m++) { acc[m][0] = make_float2(0.f, 0.f); acc[m][1] = make_float2(0.f, 0.f); }

#pragma unroll 2
        for (int d4 = 0; d4 < C_ / 4; d4++) {
            float4 xr[8];
#pragma unroll
            for (int m = 0; m < 8; m++) xr[m] = xb[m * 32 + d4];
#pragma unroll
            for (int q = 0; q < 4; q++) {
                float4 w4 = *(const float4*)&W2s[(d4 * 4 + q) * C_ + lane * 4];
                float2 wlo = make_float2(w4.x, w4.y);
                float2 whi = make_float2(w4.z, w4.w);
#pragma unroll
                for (int m = 0; m < 8; m++) {
                    float xv = (q == 0) ? xr[m].x : (q == 1) ? xr[m].y : (q == 2) ? xr[m].z : xr[m].w;
                    float2 xx = make_float2(xv, xv);
                    acc[m][0] = ffma2(wlo, xx, acc[m][0]);
                    acc[m][1] = ffma2(whi, xx, acc[m][1]);
                }
            }
        }

        // ---------------- GN2 + SiLU + layer 3 + KL ----------------
        float kacc = 0.0f;
#pragma unroll
        for (int m = 0; m < 8; m++) {
            float v0 = acc[m][0].x + bias2.x;
            float v1 = acc[m][0].y + bias2.y;
            float v2 = acc[m][1].x + bias2.z;
            float v3 = acc[m][1].y + bias2.w;
            float s  = v0 + v1 + v2 + v3;
            float ss = v0 * v0 + v1 * v1 + v2 * v2 + v3 * v3;
#pragma unroll
            for (int o = 16; o > 0; o >>= 1) {
                s  += __shfl_xor_sync(0xffffffffu, s,  o);
                ss += __shfl_xor_sync(0xffffffffu, ss, o);
            }
            float mu  = s * (1.0f / 128.0f);
            float var = ss * (1.0f / 128.0f) - mu * mu;
            float inv = rsqrtf(var + 1e-5f);
            float h0 = silu_f((v0 - mu) * inv * gw2.x + gb2.x);
            float h1 = silu_f((v1 - mu) * inv * gw2.y + gb2.y);
            float h2 = silu_f((v2 - mu) * inv * gw2.z + gb2.z);
            float h3 = silu_f((v3 - mu) * inv * gw2.w + gb2.w);

            float p0 = h0 * w30.x + h1 * w30.y + h2 * w30.z + h3 * w30.w;
            float p1 = h0 * w31.x + h1 * w31.y + h2 * w31.z + h3 * w31.w;
#pragma unroll
            for (int o = 16; o > 0; o >>= 1) {
                p0 += __shfl_xor_sync(0xffffffffu, p0, o);
                p1 += __shfl_xor_sync(0xffffffffu, p1, o);
            }
            if (lane == 0) {
                float o0 = p0 + b3_0, o1 = p1 + b3_1;
                float pm = tanhf(o0 * isc0) * sc0;
                float pl = tanhf(o1 * isc1) * sc1;
                float dmu = zmn - pm;
                kacc += pl - zl + (__expf(2.0f * zl) + dmu * dmu) * 0.5f * __expf(-2.0f * pl) - 0.5f;
            }
        }
        if (lane == 0) atomicAdd(out + b, kacc * 0.125f);
    }
}

extern "C" void kernel_launch(void* const* d_in, const int* in_sizes, int n_in,
                              void* d_out, int out_size) {
    const float* z_sample      = (const float*)d_in[0];
    const int*   target        = (const int*)  d_in[1];
    const float* z_mean        = (const float*)d_in[2];
    const float* z_logstd      = (const float*)d_in[3];
    const float* z_shared      = (const float*)d_in[4];
    const float* u_gumbel      = (const float*)d_in[5];
    const float* u_adj         = (const float*)d_in[6];
    const float* target_params = (const float*)d_in[7];
    const float* enco_theta    = (const float*)d_in[8];
    const float* enco_gamma    = (const float*)d_in[9];
    const float* W1            = (const float*)d_in[10];
    const float* b1            = (const float*)d_in[11];
    const float* gn1_w         = (const float*)d_in[12];
    const float* gn1_b         = (const float*)d_in[13];
    const float* W2            = (const float*)d_in[14];
    const float* b2            = (const float*)d_in[15];
    const float* gn2_w         = (const float*)d_in[16];
    const float* gn2_b         = (const float*)d_in[17];
    const float* W3            = (const float*)d_in[18];
    const float* b3            = (const float*)d_in[19];
    const float* tanh_scale    = (const float*)d_in[20];
    float* out = (float*)d_out;

    prep_kernel<<<B_, L_>>>(target_params, u_gumbel, enco_theta, enco_gamma, out);

    cudaFuncSetAttribute(main_kernel, cudaFuncAttributeMaxDynamicSharedMemorySize, SMEM_BYTES);
    main_kernel<<<GRID_MAIN, 256, SMEM_BYTES>>>(
        z_sample, target, z_mean, z_logstd, z_shared, u_adj,
        W1, b1, gn1_w, gn1_b, W2, b2, gn2_w, gn2_b, W3, b3, tanh_scale, out);
}

// round 3
// speedup vs baseline: 1.4447x; 1.0033x over previous
#include <cuda_runtime.h>
#include <math.h>

#define B_   1024
#define L_   32
#define K_   8
#define G_   8
#define C_   128
#define S_   32
#define DIN_ 104
#define GRID_MAIN 152
#define NITEMS (L_ * 128)      // 32 latents x 128 chunks (chunk = 64 rows = 8 warps x 8 rows)

// scratch (module-level, allocation-free)
__device__ unsigned char g_ci[B_ * L_];
__device__ float g_ep[K_ * K_];

// packed dual-FMA: ptxas only emits FFMA2 from PTX fma.rn.f32x2
__device__ __forceinline__ float2 ffma2(float2 a, float2 b, float2 c) {
    union U { float2 f; unsigned long long u; };
    U A, Bv, Cv, D;
    A.f = a; Bv.f = b; Cv.f = c;
    asm("fma.rn.f32x2 %0, %1, %2, %3;" : "=l"(D.u) : "l"(A.u), "l"(Bv.u), "l"(Cv.u));
    return D.f;
}

__device__ __forceinline__ float silu_f(float x) {
    return x * (1.0f / (1.0f + __expf(-x)));
}

__global__ void prep_kernel(const float* __restrict__ tp,   // target_params [L,K]
                            const float* __restrict__ ug,   // u_gumbel [B,L,K]
                            const float* __restrict__ th,   // enco_theta [K,K]
                            const float* __restrict__ ga,   // enco_gamma [K,K]
                            float* __restrict__ out) {
    int b = blockIdx.x, l = threadIdx.x;
    const float* u = ug + (b * L_ + l) * K_;
    float best = -1e30f; int bi = 0;
#pragma unroll
    for (int k = 0; k < K_; k++) {
        float gum = -logf(-logf(u[k] + 1e-10f) + 1e-10f);
        float v = tp[l * K_ + k] + gum;
        if (v > best) { best = v; bi = k; }
    }
    g_ci[b * L_ + l] = (unsigned char)bi;
    if (l == 0) out[b] = 0.0f;
    if (b == 0) {
        for (int e = l; e < K_ * K_; e += L_) {
            float s1 = 1.0f / (1.0f + expf(-th[e]));
            float s2 = 1.0f / (1.0f + expf(-ga[e]));
            g_ep[e] = s1 * s2;
        }
    }
}

// SMEM layout (floats):
// W1s [104][128] = 13312 | W2s [128][128] = 16384 | W3s [2][128] = 256
// b1,g1w,g1b,b2,g2w,g2b = 768 | eps 64 | bts 4  -> 30788
// buf: 8 warps * 8 rows * 128 floats = 8192
#define SMEM_FLOATS (30788 + 8192)
#define SMEM_BYTES  (SMEM_FLOATS * 4)

__global__ __launch_bounds__(256, 1) void main_kernel(
    const float* __restrict__ z_sample, const int* __restrict__ target,
    const float* __restrict__ z_mean,   const float* __restrict__ z_logstd,
    const float* __restrict__ z_shared, const float* __restrict__ u_adj,
    const float* __restrict__ W1, const float* __restrict__ b1g,
    const float* __restrict__ g1wg, const float* __restrict__ g1bg,
    const float* __restrict__ W2, const float* __restrict__ b2g,
    const float* __restrict__ g2wg, const float* __restrict__ g2bg,
    const float* __restrict__ W3, const float* __restrict__ b3g,
    const float* __restrict__ tsc, float* __restrict__ out)
{
    extern __shared__ float sm[];
    float* W1s  = sm;            // 13312
    float* W2s  = sm + 13312;    // 16384
    float* W3s  = sm + 29696;    // 256
    float* sb1  = sm + 29952;
    float* sg1w = sm + 30080;
    float* sg1b = sm + 30208;
    float* sb2  = sm + 30336;
    float* sg2w = sm + 30464;
    float* sg2b = sm + 30592;
    float* seps = sm + 30720;    // 64
    float* sbts = sm + 30784;    // 4
    float* buf  = sm + 30788;    // 8 warps * 1024

    const int tid = threadIdx.x;
    const int w = tid >> 5, lane = tid & 31;
    float* mybuf = buf + w * 1024;

    const int start = (int)(((long long)blockIdx.x * NITEMS) / gridDim.x);
    const int end   = (int)(((long long)(blockIdx.x + 1) * NITEMS) / gridDim.x);

    int cur_l = -1;
    float4 bias1, gw1, gb1, bias2, gw2, gb2, w30, w31;
    float b3_0 = 0.f, b3_1 = 0.f, sc0 = 1.f, sc1 = 1.f, isc0 = 1.f, isc1 = 1.f;

    for (int item = start; item < end; item++) {
        const int l = item >> 7;
        const int ch = item & 127;

        if (l != cur_l) {
            __syncthreads();
            // transposed weight copies: smem [d][c]
            const float* W1g = W1 + l * C_ * DIN_;
            for (int idx = tid; idx < C_ * DIN_; idx += 256) {
                int d = idx >> 7, c = idx & 127;
                W1s[idx] = W1g[c * DIN_ + d];
            }
            const float* W2g = W2 + l * C_ * C_;
            for (int idx = tid; idx < C_ * C_; idx += 256) {
                int d = idx >> 7, c = idx & 127;
                W2s[idx] = W2g[c * C_ + d];
            }
            for (int idx = tid; idx < 2 * C_; idx += 256) W3s[idx] = W3[l * 2 * C_ + idx];
            if (tid < C_) {
                sb1[tid]  = b1g[l * C_ + tid];
                sg1w[tid] = g1wg[l * C_ + tid];
                sg1b[tid] = g1bg[l * C_ + tid];
                sb2[tid]  = b2g[l * C_ + tid];
                sg2w[tid] = g2wg[l * C_ + tid];
                sg2b[tid] = g2bg[l * C_ + tid];
            }
            if (tid < 64) seps[tid] = g_ep[tid];
            if (tid < 2) sbts[tid] = b3g[l * 2 + tid];
            else if (tid < 4) sbts[tid] = tsc[l * 2 + tid - 2];
            __syncthreads();

            bias1 = *(const float4*)&sb1[lane * 4];
            gw1   = *(const float4*)&sg1w[lane * 4];
            gb1   = *(const float4*)&sg1b[lane * 4];
            bias2 = *(const float4*)&sb2[lane * 4];
            gw2   = *(const float4*)&sg2w[lane * 4];
            gb2   = *(const float4*)&sg2b[lane * 4];
            w30   = *(const float4*)&W3s[lane * 4];
            w31   = *(const float4*)&W3s[128 + lane * 4];
            b3_0 = sbts[0]; b3_1 = sbts[1];
            sc0 = __expf(sbts[2]); sc1 = __expf(sbts[3]);
            isc0 = 1.0f / sc0; isc1 = 1.0f / sc1;
            cur_l = l;
        }

        const int b = ch * 8 + w;                 // one batch element, all 8 graphs
        const int cl  = g_ci[b * L_ + l];
        const int cj  = g_ci[b * L_ + lane];
        const int tgt = target[b];
        const float zs  = z_sample[b * L_ + lane];
        const float zsh = z_shared[b * S_ + lane];
        const float epv = seps[cj * K_ + cl];
        const float notdiag = (lane != l) ? 1.0f : 0.0f;
        const float tv = (lane < 8) ? (((lane == tgt) && (cl == tgt)) ? 1.0f : 0.0f) : 0.0f;
        const float zl  = z_logstd[b * L_ + l];
        const float zmn = z_mean[b * L_ + l];

        __syncwarp();
#pragma unroll
        for (int m = 0; m < 8; m++) {
            float u = u_adj[((b * G_ + m) * K_ + cj) * K_ + cl];
            float mk = (u < epv) ? notdiag : 0.0f;
            mybuf[m * 128 + lane]      = mk * zs;
            mybuf[m * 128 + 32 + lane] = mk;
            if (lane < 8) mybuf[m * 128 + 64 + lane] = tv;
            mybuf[m * 128 + 72 + lane] = zsh;
        }
        __syncwarp();

        const float4* xb = (const float4*)mybuf;   // row m at xb + m*32

        // ---------------- layer 1: [104] -> [128] ----------------
        float2 acc[8][2];
#pragma unroll
        for (int m = 0; m < 8; m++) { acc[m][0] = make_float2(0.f, 0.f); acc[m][1] = make_float2(0.f, 0.f); }

#pragma unroll 2
        for (int d4 = 0; d4 < DIN_ / 4; d4++) {
            float4 xr[8];
#pragma unroll
            for (int m = 0; m < 8; m++) xr[m] = xb[m * 32 + d4];
#pragma unroll
            for (int q = 0; q < 4; q++) {
                float4 w4 = *(const float4*)&W1s[(d4 * 4 + q) * C_ + lane * 4];
                float2 wlo = make_float2(w4.x, w4.y);
                float2 whi = make_float2(w4.z, w4.w);
#pragma unroll
                for (int m = 0; m < 8; m++) {
                    float xv = (q == 0) ? xr[m].x : (q == 1) ? xr[m].y : (q == 2) ? xr[m].z : xr[m].w;
                    float2 xx = make_float2(xv, xv);
                    acc[m][0] = ffma2(wlo, xx, acc[m][0]);
                    acc[m][1] = ffma2(whi, xx, acc[m][1]);
                }
            }
        }
        __syncwarp();

        // ---------------- GN1 + SiLU ----------------
#pragma unroll
        for (int m = 0; m < 8; m++) {
            float v0 = acc[m][0].x + bias1.x;
            float v1 = acc[m][0].y + bias1.y;
            float v2 = acc[m][1].x + bias1.z;
            float v3 = acc[m][1].y + bias1.w;
            float s  = v0 + v1 + v2 + v3;
            float ss = v0 * v0 + v1 * v1 + v2 * v2 + v3 * v3;
#pragma unroll
            for (int o = 16; o > 0; o >>= 1) {
                s  += __shfl_xor_sync(0xffffffffu, s,  o);
                ss += __shfl_xor_sync(0xffffffffu, ss, o);
            }
            float mu  = s * (1.0f / 128.0f);
            float var = ss * (1.0f / 128.0f) - mu * mu;
            float inv = rsqrtf(var + 1e-5f);
            float h0 = silu_f((v0 - mu) * inv * gw1.x + gb1.x);
            float h1 = silu_f((v1 - mu) * inv * gw1.y + gb1.y);
            float h2 = silu_f((v2 - mu) * inv * gw1.z + gb1.z);
            float h3 = silu_f((v3 - mu) * inv * gw1.w + gb1.w);
            *(float4*)&mybuf[m * 128 + lane * 4] = make_float4(h0, h1, h2, h3);
        }
        __syncwarp();

        // ---------------- layer 2: [128] -> [128] ----------------
#pragma unroll
        for (int m = 0; m < 8; m++) { acc[m][0] = make_float2(0.f, 0.f); acc[m][1] = make_float2(0.f, 0.f); }

#pragma unroll 2
        for (int d4 = 0; d4 < C_ / 4; d4++) {
            float4 xr[8];
#pragma unroll
            for (int m = 0; m < 8; m++) xr[m] = xb[m * 32 + d4];
#pragma unroll
            for (int q = 0; q < 4; q++) {
                float4 w4 = *(const float4*)&W2s[(d4 * 4 + q) * C_ + lane * 4];
                float2 wlo = make_float2(w4.x, w4.y);
                float2 whi = make_float2(w4.z, w4.w);
#pragma unroll
                for (int m = 0; m < 8; m++) {
                    float xv = (q == 0) ? xr[m].x : (q == 1) ? xr[m].y : (q == 2) ? xr[m].z : xr[m].w;
                    float2 xx = make_float2(xv, xv);
                    acc[m][0] = ffma2(wlo, xx, acc[m][0]);
                    acc[m][1] = ffma2(whi, xx, acc[m][1]);
                }
            }
        }

        // ---------------- GN2 + SiLU + layer 3 + KL ----------------
        float kacc = 0.0f;
#pragma unroll
        for (int m = 0; m < 8; m++) {
            float v0 = acc[m][0].x + bias2.x;
            float v1 = acc[m][0].y + bias2.y;
            float v2 = acc[m][1].x + bias2.z;
            float v3 = acc[m][1].y + bias2.w;
            float s  = v0 + v1 + v2 + v3;
            float ss = v0 * v0 + v1 * v1 + v2 * v2 + v3 * v3;
#pragma unroll
            for (int o = 16; o > 0; o >>= 1) {
                s  += __shfl_xor_sync(0xffffffffu, s,  o);
                ss += __shfl_xor_sync(0xffffffffu, ss, o);
            }
            float mu  = s * (1.0f / 128.0f);
            float var = ss * (1.0f / 128.0f) - mu * mu;
            float inv = rsqrtf(var + 1e-5f);
            float h0 = silu_f((v0 - mu) * inv * gw2.x + gb2.x);
            float h1 = silu_f((v1 - mu) * inv * gw2.y + gb2.y);
            float h2 = silu_f((v2 - mu) * inv * gw2.z + gb2.z);
            float h3 = silu_f((v3 - mu) * inv * gw2.w + gb2.w);

            float p0 = h0 * w30.x + h1 * w30.y + h2 * w30.z + h3 * w30.w;
            float p1 = h0 * w31.x + h1 * w31.y + h2 * w31.z + h3 * w31.w;
#pragma unroll
            for (int o = 16; o > 0; o >>= 1) {
                p0 += __shfl_xor_sync(0xffffffffu, p0, o);
                p1 += __shfl_xor_sync(0xffffffffu, p1, o);
            }
            if (lane == 0) {
                float o0 = p0 + b3_0, o1 = p1 + b3_1;
                float pm = tanhf(o0 * isc0) * sc0;
                float pl = tanhf(o1 * isc1) * sc1;
                float dmu = zmn - pm;
                kacc += pl - zl + (__expf(2.0f * zl) + dmu * dmu) * 0.5f * __expf(-2.0f * pl) - 0.5f;
            }
        }
        if (lane == 0) atomicAdd(out + b, kacc * 0.125f);
    }
}

extern "C" void kernel_launch(void* const* d_in, const int* in_sizes, int n_in,
                              void* d_out, int out_size) {
    const float* z_sample      = (const float*)d_in[0];
    const int*   target        = (const int*)  d_in[1];
    const float* z_mean        = (const float*)d_in[2];
    const float* z_logstd      = (const float*)d_in[3];
    const float* z_shared      = (const float*)d_in[4];
    const float* u_gumbel      = (const float*)d_in[5];
    const float* u_adj         = (const float*)d_in[6];
    const float* target_params = (const float*)d_in[7];
    const float* enco_theta    = (const float*)d_in[8];
    const float* enco_gamma    = (const float*)d_in[9];
    const float* W1            = (const float*)d_in[10];
    const float* b1            = (const float*)d_in[11];
    const float* gn1_w         = (const float*)d_in[12];
    const float* gn1_b         = (const float*)d_in[13];
    const float* W2            = (const float*)d_in[14];
    const float* b2            = (const float*)d_in[15];
    const float* gn2_w         = (const float*)d_in[16];
    const float* gn2_b         = (const float*)d_in[17];
    const float* W3            = (const float*)d_in[18];
    const float* b3            = (const float*)d_in[19];
    const float* tanh_scale    = (const float*)d_in[20];
    float* out = (float*)d_out;

    prep_kernel<<<B_, L_>>>(target_params, u_gumbel, enco_theta, enco_gamma, out);

    cudaFuncSetAttribute(main_kernel, cudaFuncAttributeMaxDynamicSharedMemorySize, SMEM_BYTES);
    main_kernel<<<GRID_MAIN, 256, SMEM_BYTES>>>(
        z_sample, target, z_mean, z_logstd, z_shared, u_adj,
        W1, b1, gn1_w, gn1_b, W2, b2, gn2_w, gn2_b, W3, b3, tanh_scale, out);
}

// round 5
// speedup vs baseline: 2.4807x; 1.7171x over previous
#include <cuda_runtime.h>
#include <cuda_bf16.h>
#include <math.h>

#define B_   1024
#define L_   32
#define K_   8
#define G_   8
#define C_   128
#define S_   32
#define GRID_MAIN 148
#define NTILES 64
#define NITEMS (L_ * NTILES)

__device__ unsigned char g_ci[B_ * L_];
__device__ float g_ep[K_ * K_];
__device__ unsigned int g_mask[B_ * G_ * L_];

// ---------- helpers ----------
__device__ __forceinline__ unsigned pack2(float lo, float hi) {
    unsigned r;
    asm("cvt.rn.bf16x2.f32 %0, %1, %2;" : "=r"(r) : "f"(hi), "f"(lo));
    return r;
}
__device__ __forceinline__ void split2(float x0, float x1, unsigned& uh, unsigned& ul) {
    uh = pack2(x0, x1);
    __nv_bfloat162 hv = *reinterpret_cast<__nv_bfloat162*>(&uh);
    ul = pack2(x0 - __low2float(hv), x1 - __high2float(hv));
}
__device__ __forceinline__ float silu_f(float x) {
    return x * (1.0f / (1.0f + __expf(-x)));
}
__device__ __forceinline__ void mma_bf16(float* c,
    unsigned a0, unsigned a1, unsigned a2, unsigned a3, unsigned b0, unsigned b1) {
    asm("mma.sync.aligned.m16n8k16.row.col.f32.bf16.bf16.f32 "
        "{%0,%1,%2,%3},{%4,%5,%6,%7},{%8,%9},{%0,%1,%2,%3};"
        : "+f"(c[0]), "+f"(c[1]), "+f"(c[2]), "+f"(c[3])
        : "r"(a0), "r"(a1), "r"(a2), "r"(a3), "r"(b0), "r"(b1));
}
__device__ __forceinline__ float xval(int d, unsigned Mw, bool tfl, int tgt,
                                      const float* zr, const float* zh) {
    if (d < 32)  return ((Mw >> d) & 1u) ? zr[d] : 0.0f;
    if (d < 64)  return (float)((Mw >> (d - 32)) & 1u);
    if (d < 72)  return (tfl && (d - 64) == tgt) ? 1.0f : 0.0f;
    if (d < 104) return zh[d - 72];
    return 0.0f;
}

// ---------- prep ----------
__global__ void prep_kernel(const float* __restrict__ tp, const float* __restrict__ ug,
                            const float* __restrict__ th, const float* __restrict__ ga,
                            float* __restrict__ out) {
    int b = blockIdx.x, l = threadIdx.x;
    const float* u = ug + (b * L_ + l) * K_;
    float best = -1e30f; int bi = 0;
#pragma unroll
    for (int k = 0; k < K_; k++) {
        float gum = -logf(-logf(u[k] + 1e-10f) + 1e-10f);
        float v = tp[l * K_ + k] + gum;
        if (v > best) { best = v; bi = k; }
    }
    g_ci[b * L_ + l] = (unsigned char)bi;
    if (l == 0) out[b] = 0.0f;
    if (b == 0) {
        for (int e = l; e < K_ * K_; e += L_) {
            float s1 = 1.0f / (1.0f + expf(-th[e]));
            float s2 = 1.0f / (1.0f + expf(-ga[e]));
            g_ep[e] = s1 * s2;
        }
    }
}

__global__ void prep2_kernel(const float* __restrict__ u_adj) {
    __shared__ unsigned char sc[L_];
    __shared__ float sep[K_ * K_];
    int b = blockIdx.x, t = threadIdx.x;
    int g = t >> 5, l = t & 31;
    if (t < L_) sc[t] = g_ci[b * L_ + t];
    if (t >= 64 && t < 128) sep[t - 64] = g_ep[t - 64];
    __syncthreads();
    int cl = sc[l];
    unsigned bits = 0;
#pragma unroll
    for (int cj = 0; cj < K_; cj++) {
        float u = u_adj[((b * G_ + g) * K_ + cj) * K_ + cl];
        bits |= (u < sep[cj * K_ + cl]) ? (1u << cj) : 0u;
    }
    unsigned wv = 0;
#pragma unroll
    for (int j = 0; j < L_; j++) {
        unsigned mj = (bits >> sc[j]) & 1u;
        if (j == l) mj = 0;
        wv |= mj << j;
    }
    g_mask[(b * G_ + g) * L_ + l] = wv;
}

// ---------- smem layout (bytes) ----------
// W1q: 128 rows x 29 uint4 (28 used + pad)  = 59392
// W2q: 128 rows x 33 uint4 (32 used + pad)  = 67584
#define OFF_W1   0
#define OFF_W2   59392
#define OFF_SZS  126976
#define OFF_SZSH 129024
#define OFF_B1   131072
#define OFF_G1W  131584
#define OFF_G1B  132096
#define OFF_B2   132608
#define OFF_G2W  133120
#define OFF_G2B  133632
#define OFF_W3   134144
#define SMEM_BYTES 135168

__global__ __launch_bounds__(256, 1) void main_kernel(
    const float* __restrict__ z_sample, const int* __restrict__ target,
    const float* __restrict__ z_mean,   const float* __restrict__ z_logstd,
    const float* __restrict__ z_shared,
    const float* __restrict__ W1, const float* __restrict__ b1g,
    const float* __restrict__ g1wg, const float* __restrict__ g1bg,
    const float* __restrict__ W2, const float* __restrict__ b2g,
    const float* __restrict__ g2wg, const float* __restrict__ g2bg,
    const float* __restrict__ W3g, const float* __restrict__ b3g,
    const float* __restrict__ tsc, float* __restrict__ out)
{
    extern __shared__ char smem[];
    uint4*  W1q  = (uint4*)(smem + OFF_W1);
    uint4*  W2q  = (uint4*)(smem + OFF_W2);
    float*  szs  = (float*)(smem + OFF_SZS);
    float*  szsh = (float*)(smem + OFF_SZSH);
    float2* sB1  = (float2*)(smem + OFF_B1);
    float2* sG1w = (float2*)(smem + OFF_G1W);
    float2* sG1b = (float2*)(smem + OFF_G1B);
    float2* sB2  = (float2*)(smem + OFF_B2);
    float2* sG2w = (float2*)(smem + OFF_G2W);
    float2* sG2b = (float2*)(smem + OFF_G2B);
    float4* sW3  = (float4*)(smem + OFF_W3);

    const int tid = threadIdx.x;
    const int wid = tid >> 5;
    const int lane = tid & 31;
    const int gid = lane >> 2;
    const int t4 = lane & 3;

    const int start = (int)(((long long)blockIdx.x * NITEMS) / GRID_MAIN);
    const int end   = (int)(((long long)(blockIdx.x + 1) * NITEMS) / GRID_MAIN);

    int cur_l = -1;
    float b3_0 = 0.f, b3_1 = 0.f, sc0 = 1.f, sc1 = 1.f, isc0 = 1.f, isc1 = 1.f;

    for (int item = start; item < end; item++) {
        const int l = item >> 6;
        const int tile = item & 63;

        if (l != cur_l) {
            __syncthreads();
            // W1 -> interleaved hi/lo uint4 per (c, kk, t4): {b0hi, b1hi, b0lo, b1lo}
            const float* W1g = W1 + l * C_ * 104;
            for (int idx = tid; idx < 128 * 28; idx += 256) {
                int c = idx / 28, q = idx - c * 28;
                int kk = q >> 2, tq = q & 3;
                int d0 = kk * 16 + tq * 2, d1 = d0 + 8;
                float w00 = W1g[c * 104 + d0];
                float w01 = W1g[c * 104 + d0 + 1];
                float w10 = (d1     < 104) ? W1g[c * 104 + d1]     : 0.0f;
                float w11 = (d1 + 1 < 104) ? W1g[c * 104 + d1 + 1] : 0.0f;
                unsigned h0, l0, h1, l1;
                split2(w00, w01, h0, l0);
                split2(w10, w11, h1, l1);
                W1q[c * 29 + q] = make_uint4(h0, h1, l0, l1);
            }
            const float* W2g = W2 + l * C_ * C_;
            for (int idx = tid; idx < 128 * 32; idx += 256) {
                int c = idx >> 5, q = idx & 31;
                int kk = q >> 2, tq = q & 3;
                int d0 = kk * 16 + tq * 2, d1 = d0 + 8;
                float w00 = W2g[c * C_ + d0];
                float w01 = W2g[c * C_ + d0 + 1];
                float w10 = W2g[c * C_ + d1];
                float w11 = W2g[c * C_ + d1 + 1];
                unsigned h0, l0, h1, l1;
                split2(w00, w01, h0, l0);
                split2(w10, w11, h1, l1);
                W2q[c * 33 + q] = make_uint4(h0, h1, l0, l1);
            }
            if (tid < 64) {
                sB1[tid]  = ((const float2*)(b1g  + l * C_))[tid];
                sG1w[tid] = ((const float2*)(g1wg + l * C_))[tid];
                sG1b[tid] = ((const float2*)(g1bg + l * C_))[tid];
                sB2[tid]  = ((const float2*)(b2g  + l * C_))[tid];
                sG2w[tid] = ((const float2*)(g2wg + l * C_))[tid];
                sG2b[tid] = ((const float2*)(g2bg + l * C_))[tid];
                int c0 = 2 * tid;
                sW3[tid] = make_float4(W3g[l * 2 * C_ + c0], W3g[l * 2 * C_ + C_ + c0],
                                       W3g[l * 2 * C_ + c0 + 1], W3g[l * 2 * C_ + C_ + c0 + 1]);
            }
            b3_0 = b3g[l * 2]; b3_1 = b3g[l * 2 + 1];
            sc0 = __expf(tsc[l * 2]); sc1 = __expf(tsc[l * 2 + 1]);
            isc0 = 1.0f / sc0; isc1 = 1.0f / sc1;
            __syncthreads();
            cur_l = l;
        }

        // stage z rows for this tile (16 b's)
        __syncthreads();
        for (int idx = tid; idx < 512; idx += 256) {
            szs[idx]  = z_sample[tile * 16 * L_ + idx];
            szsh[idx] = z_shared[tile * 16 * S_ + idx];
        }
        __syncthreads();

        // per-thread rows: r0 = wid*16+gid, r1 = r0+8
        const int grow0 = tile * 128 + wid * 16 + gid;
        const int grow1 = grow0 + 8;
        const int b0i = grow0 >> 3, b1i = grow1 >> 3;
        const unsigned Mw0 = g_mask[grow0 * L_ + l];
        const unsigned Mw1 = g_mask[grow1 * L_ + l];
        const int tgt0 = target[b0i], tgt1 = target[b1i];
        const bool tf0 = (g_ci[b0i * L_ + l] == tgt0);
        const bool tf1 = (g_ci[b1i * L_ + l] == tgt1);
        const float* zr0 = szs  + (2 * wid) * 32;
        const float* zr1 = zr0 + 32;
        const float* zh0 = szsh + (2 * wid) * 32;
        const float* zh1 = zh0 + 32;

        // ---- build A1 fragments ----
        unsigned Ah[7][4], Al[7][4];
#pragma unroll
        for (int kk = 0; kk < 7; kk++) {
            int db = kk * 16 + t4 * 2;
            split2(xval(db, Mw0, tf0, tgt0, zr0, zh0),
                   xval(db + 1, Mw0, tf0, tgt0, zr0, zh0), Ah[kk][0], Al[kk][0]);
            split2(xval(db, Mw1, tf1, tgt1, zr1, zh1),
                   xval(db + 1, Mw1, tf1, tgt1, zr1, zh1), Ah[kk][1], Al[kk][1]);
            split2(xval(db + 8, Mw0, tf0, tgt0, zr0, zh0),
                   xval(db + 9, Mw0, tf0, tgt0, zr0, zh0), Ah[kk][2], Al[kk][2]);
            split2(xval(db + 8, Mw1, tf1, tgt1, zr1, zh1),
                   xval(db + 9, Mw1, tf1, tgt1, zr1, zh1), Ah[kk][3], Al[kk][3]);
        }

        // ---- MMA1 ----
        float acc[16][4];
#pragma unroll
        for (int nt = 0; nt < 16; nt++)
#pragma unroll
            for (int i = 0; i < 4; i++) acc[nt][i] = 0.0f;

#pragma unroll
        for (int nt = 0; nt < 16; nt++) {
            const uint4* bp = W1q + (nt * 8 + gid) * 29 + t4;
#pragma unroll
            for (int kk = 0; kk < 7; kk++) {
                uint4 bq = bp[kk * 4];
                mma_bf16(acc[nt], Ah[kk][0], Ah[kk][1], Ah[kk][2], Ah[kk][3], bq.x, bq.y);
                mma_bf16(acc[nt], Ah[kk][0], Ah[kk][1], Ah[kk][2], Ah[kk][3], bq.z, bq.w);
                if (kk != 2 && kk != 3)
                    mma_bf16(acc[nt], Al[kk][0], Al[kk][1], Al[kk][2], Al[kk][3], bq.x, bq.y);
            }
        }

        // ---- GN1 + SiLU -> A2 fragments ----
        float s0 = 0.f, q0 = 0.f, s1 = 0.f, q1 = 0.f;
#pragma unroll
        for (int nt = 0; nt < 16; nt++) {
            float2 bb = sB1[nt * 4 + t4];
            acc[nt][0] += bb.x; acc[nt][1] += bb.y;
            acc[nt][2] += bb.x; acc[nt][3] += bb.y;
            s0 += acc[nt][0] + acc[nt][1];
            q0 += acc[nt][0] * acc[nt][0] + acc[nt][1] * acc[nt][1];
            s1 += acc[nt][2] + acc[nt][3];
            q1 += acc[nt][2] * acc[nt][2] + acc[nt][3] * acc[nt][3];
        }
#pragma unroll
        for (int o = 1; o <= 2; o <<= 1) {
            s0 += __shfl_xor_sync(0xffffffffu, s0, o);
            q0 += __shfl_xor_sync(0xffffffffu, q0, o);
            s1 += __shfl_xor_sync(0xffffffffu, s1, o);
            q1 += __shfl_xor_sync(0xffffffffu, q1, o);
        }
        float mu0 = s0 * (1.0f / 128.0f);
        float inv0 = rsqrtf(q0 * (1.0f / 128.0f) - mu0 * mu0 + 1e-5f);
        float mu1 = s1 * (1.0f / 128.0f);
        float inv1 = rsqrtf(q1 * (1.0f / 128.0f) - mu1 * mu1 + 1e-5f);

        unsigned A2h[8][4], A2l[8][4];
#pragma unroll
        for (int kk = 0; kk < 8; kk++) {
            int nt0 = 2 * kk, nt1 = 2 * kk + 1;
            float2 w0 = sG1w[nt0 * 4 + t4], c0v = sG1b[nt0 * 4 + t4];
            float2 w1 = sG1w[nt1 * 4 + t4], c1v = sG1b[nt1 * 4 + t4];
            float h00 = silu_f((acc[nt0][0] - mu0) * inv0 * w0.x + c0v.x);
            float h01 = silu_f((acc[nt0][1] - mu0) * inv0 * w0.y + c0v.y);
            float h02 = silu_f((acc[nt0][2] - mu1) * inv1 * w0.x + c0v.x);
            float h03 = silu_f((acc[nt0][3] - mu1) * inv1 * w0.y + c0v.y);
            float h10 = silu_f((acc[nt1][0] - mu0) * inv0 * w1.x + c1v.x);
            float h11 = silu_f((acc[nt1][1] - mu0) * inv0 * w1.y + c1v.y);
            float h12 = silu_f((acc[nt1][2] - mu1) * inv1 * w1.x + c1v.x);
            float h13 = silu_f((acc[nt1][3] - mu1) * inv1 * w1.y + c1v.y);
            split2(h00, h01, A2h[kk][0], A2l[kk][0]);
            split2(h02, h03, A2h[kk][1], A2l[kk][1]);
            split2(h10, h11, A2h[kk][2], A2l[kk][2]);
            split2(h12, h13, A2h[kk][3], A2l[kk][3]);
        }

        // ---- MMA2 ----
#pragma unroll
        for (int nt = 0; nt < 16; nt++)
#pragma unroll
            for (int i = 0; i < 4; i++) acc[nt][i] = 0.0f;

#pragma unroll
        for (int nt = 0; nt < 16; nt++) {
            const uint4* bp = W2q + (nt * 8 + gid) * 33 + t4;
#pragma unroll
            for (int kk = 0; kk < 8; kk++) {
                uint4 bq = bp[kk * 4];
                mma_bf16(acc[nt], A2h[kk][0], A2h[kk][1], A2h[kk][2], A2h[kk][3], bq.x, bq.y);
                mma_bf16(acc[nt], A2h[kk][0], A2h[kk][1], A2h[kk][2], A2h[kk][3], bq.z, bq.w);
                mma_bf16(acc[nt], A2l[kk][0], A2l[kk][1], A2l[kk][2], A2l[kk][3], bq.x, bq.y);
            }
        }

        // ---- GN2 + SiLU + layer3 + KL ----
        s0 = 0.f; q0 = 0.f; s1 = 0.f; q1 = 0.f;
#pragma unroll
        for (int nt = 0; nt < 16; nt++) {
            float2 bb = sB2[nt * 4 + t4];
            acc[nt][0] += bb.x; acc[nt][1] += bb.y;
            acc[nt][2] += bb.x; acc[nt][3] += bb.y;
            s0 += acc[nt][0] + acc[nt][1];
            q0 += acc[nt][0] * acc[nt][0] + acc[nt][1] * acc[nt][1];
            s1 += acc[nt][2] + acc[nt][3];
            q1 += acc[nt][2] * acc[nt][2] + acc[nt][3] * acc[nt][3];
        }
#pragma unroll
        for (int o = 1; o <= 2; o <<= 1) {
            s0 += __shfl_xor_sync(0xffffffffu, s0, o);
            q0 += __shfl_xor_sync(0xffffffffu, q0, o);
            s1 += __shfl_xor_sync(0xffffffffu, s1, o);
            q1 += __shfl_xor_sync(0xffffffffu, q1, o);
        }
        mu0 = s0 * (1.0f / 128.0f);
        inv0 = rsqrtf(q0 * (1.0f / 128.0f) - mu0 * mu0 + 1e-5f);
        mu1 = s1 * (1.0f / 128.0f);
        inv1 = rsqrtf(q1 * (1.0f / 128.0f) - mu1 * mu1 + 1e-5f);

        float p00 = 0.f, p10 = 0.f, p01 = 0.f, p11 = 0.f;
#pragma unroll
        for (int nt = 0; nt < 16; nt++) {
            float2 wv = sG2w[nt * 4 + t4], bv = sG2b[nt * 4 + t4];
            float4 w3 = sW3[nt * 4 + t4];
            float h0 = silu_f((acc[nt][0] - mu0) * inv0 * wv.x + bv.x);
            float h1 = silu_f((acc[nt][1] - mu0) * inv0 * wv.y + bv.y);
            float h2 = silu_f((acc[nt][2] - mu1) * inv1 * wv.x + bv.x);
            float h3 = silu_f((acc[nt][3] - mu1) * inv1 * wv.y + bv.y);
            p00 += h0 * w3.x + h1 * w3.z;
            p10 += h0 * w3.y + h1 * w3.w;
            p01 += h2 * w3.x + h3 * w3.z;
            p11 += h2 * w3.y + h3 * w3.w;
        }
#pragma unroll
        for (int o = 1; o <= 2; o <<= 1) {
            p00 += __shfl_xor_sync(0xffffffffu, p00, o);
            p10 += __shfl_xor_sync(0xffffffffu, p10, o);
            p01 += __shfl_xor_sync(0xffffffffu, p01, o);
            p11 += __shfl_xor_sync(0xffffffffu, p11, o);
        }
        if (t4 == 0) {
            {
                float o0 = p00 + b3_0, o1 = p10 + b3_1;
                float pm = tanhf(o0 * isc0) * sc0;
                float pl = tanhf(o1 * isc1) * sc1;
                float zl = z_logstd[b0i * L_ + l], zmn = z_mean[b0i * L_ + l];
                float dmu = zmn - pm;
                float kld = pl - zl + (__expf(2.0f * zl) + dmu * dmu) * 0.5f * __expf(-2.0f * pl) - 0.5f;
                atomicAdd(out + b0i, kld * 0.125f);
            }
            {
                float o0 = p01 + b3_0, o1 = p11 + b3_1;
                float pm = tanhf(o0 * isc0) * sc0;
                float pl = tanhf(o1 * isc1) * sc1;
                float zl = z_logstd[b1i * L_ + l], zmn = z_mean[b1i * L_ + l];
                float dmu = zmn - pm;
                float kld = pl - zl + (__expf(2.0f * zl) + dmu * dmu) * 0.5f * __expf(-2.0f * pl) - 0.5f;
                atomicAdd(out + b1i, kld * 0.125f);
            }
        }
    }
}

extern "C" void kernel_launch(void* const* d_in, const int* in_sizes, int n_in,
                              void* d_out, int out_size) {
    const float* z_sample      = (const float*)d_in[0];
    const int*   target        = (const int*)  d_in[1];
    const float* z_mean        = (const float*)d_in[2];
    const float* z_logstd      = (const float*)d_in[3];
    const float* z_shared      = (const float*)d_in[4];
    const float* u_gumbel      = (const float*)d_in[5];
    const float* u_adj         = (const float*)d_in[6];
    const float* target_params = (const float*)d_in[7];
    const float* enco_theta    = (const float*)d_in[8];
    const float* enco_gamma    = (const float*)d_in[9];
    const float* W1            = (const float*)d_in[10];
    const float* b1            = (const float*)d_in[11];
    const float* gn1_w         = (const float*)d_in[12];
    const float* gn1_b         = (const float*)d_in[13];
    const float* W2            = (const float*)d_in[14];
    const float* b2            = (const float*)d_in[15];
    const float* gn2_w         = (const float*)d_in[16];
    const float* gn2_b         = (const float*)d_in[17];
    const float* W3            = (const float*)d_in[18];
    const float* b3            = (const float*)d_in[19];
    const float* tanh_scale    = (const float*)d_in[20];
    float* out = (float*)d_out;

    prep_kernel<<<B_, L_>>>(target_params, u_gumbel, enco_theta, enco_gamma, out);
    prep2_kernel<<<B_, 256>>>(u_adj);

    cudaFuncSetAttribute(main_kernel, cudaFuncAttributeMaxDynamicSharedMemorySize, SMEM_BYTES);
    main_kernel<<<GRID_MAIN, 256, SMEM_BYTES>>>(
        z_sample, target, z_mean, z_logstd, z_shared,
        W1, b1, gn1_w, gn1_b, W2, b2, gn2_w, gn2_b, W3, b3, tanh_scale, out);
}

// round 6
// speedup vs baseline: 5.3069x; 2.1393x over previous
#include <cuda_runtime.h>
#include <cuda_fp16.h>
#include <math.h>

#define B_   1024
#define L_   32
#define K_   8
#define G_   8
#define C_   128
#define S_   32
#define GRID_MAIN 296
#define NTILES 64
#define NITEMS (L_ * NTILES)

__device__ unsigned char g_ci[B_ * L_];
__device__ float g_ep[K_ * K_];
__device__ unsigned int g_mask[B_ * G_ * L_];

// ---------- helpers ----------
__device__ __forceinline__ unsigned pack2h(float lo, float hi) {
    unsigned r;
    asm("cvt.rn.f16x2.f32 %0, %1, %2;" : "=r"(r) : "f"(hi), "f"(lo));
    return r;
}
__device__ __forceinline__ float silu_f(float x) {
    return x * (1.0f / (1.0f + __expf(-x)));
}
__device__ __forceinline__ void mma_f16(float* c,
    unsigned a0, unsigned a1, unsigned a2, unsigned a3, unsigned b0, unsigned b1) {
    asm("mma.sync.aligned.m16n8k16.row.col.f32.f16.f16.f32 "
        "{%0,%1,%2,%3},{%4,%5,%6,%7},{%8,%9},{%0,%1,%2,%3};"
        : "+f"(c[0]), "+f"(c[1]), "+f"(c[2]), "+f"(c[3])
        : "r"(a0), "r"(a1), "r"(a2), "r"(a3), "r"(b0), "r"(b1));
}
__device__ __forceinline__ float xval(int d, unsigned Mw, bool tfl, int tgt,
                                      const float* zr, const float* zh) {
    if (d < 32)  return ((Mw >> d) & 1u) ? zr[d] : 0.0f;
    if (d < 64)  return (float)((Mw >> (d - 32)) & 1u);
    if (d < 72)  return (tfl && (d - 64) == tgt) ? 1.0f : 0.0f;
    if (d < 104) return zh[d - 72];
    return 0.0f;
}

// ---------- prep ----------
__global__ void prep_kernel(const float* __restrict__ tp, const float* __restrict__ ug,
                            const float* __restrict__ th, const float* __restrict__ ga,
                            float* __restrict__ out) {
    int b = blockIdx.x, l = threadIdx.x;
    const float* u = ug + (b * L_ + l) * K_;
    float best = -1e30f; int bi = 0;
#pragma unroll
    for (int k = 0; k < K_; k++) {
        float gum = -logf(-logf(u[k] + 1e-10f) + 1e-10f);
        float v = tp[l * K_ + k] + gum;
        if (v > best) { best = v; bi = k; }
    }
    g_ci[b * L_ + l] = (unsigned char)bi;
    if (l == 0) out[b] = 0.0f;
    if (b == 0) {
        for (int e = l; e < K_ * K_; e += L_) {
            float s1 = 1.0f / (1.0f + expf(-th[e]));
            float s2 = 1.0f / (1.0f + expf(-ga[e]));
            g_ep[e] = s1 * s2;
        }
    }
}

__global__ void prep2_kernel(const float* __restrict__ u_adj) {
    __shared__ unsigned char sc[L_];
    __shared__ float sep[K_ * K_];
    int b = blockIdx.x, t = threadIdx.x;
    int g = t >> 5, l = t & 31;
    if (t < L_) sc[t] = g_ci[b * L_ + t];
    if (t >= 64 && t < 128) sep[t - 64] = g_ep[t - 64];
    __syncthreads();
    int cl = sc[l];
    unsigned bits = 0;
#pragma unroll
    for (int cj = 0; cj < K_; cj++) {
        float u = u_adj[((b * G_ + g) * K_ + cj) * K_ + cl];
        bits |= (u < sep[cj * K_ + cl]) ? (1u << cj) : 0u;
    }
    unsigned wv = 0;
#pragma unroll
    for (int j = 0; j < L_; j++) {
        unsigned mj = (bits >> sc[j]) & 1u;
        if (j == l) mj = 0;
        wv |= mj << j;
    }
    g_mask[(b * G_ + g) * L_ + l] = wv;
}

// ---------- smem layout (bytes) ----------
// W1q: 128 rows x 28 uint2 = 28672   (stride 28 uint2: 56 floats == 24 mod 32 -> conflict-free)
// W2q: 128 rows x 36 uint2 = 36864   (stride 36 uint2: 72 floats == 8 mod 32  -> conflict-free)
#define OFF_W1   0
#define OFF_W2   28672
#define OFF_SZS  65536
#define OFF_SZSH 67584
#define OFF_B1   69632
#define OFF_G1W  70144
#define OFF_G1B  70656
#define OFF_B2   71168
#define OFF_G2W  71680
#define OFF_G2B  72192
#define OFF_W3   72704
#define SMEM_BYTES 73728

__global__ __launch_bounds__(256, 2) void main_kernel(
    const float* __restrict__ z_sample, const int* __restrict__ target,
    const float* __restrict__ z_mean,   const float* __restrict__ z_logstd,
    const float* __restrict__ z_shared,
    const float* __restrict__ W1, const float* __restrict__ b1g,
    const float* __restrict__ g1wg, const float* __restrict__ g1bg,
    const float* __restrict__ W2, const float* __restrict__ b2g,
    const float* __restrict__ g2wg, const float* __restrict__ g2bg,
    const float* __restrict__ W3g, const float* __restrict__ b3g,
    const float* __restrict__ tsc, float* __restrict__ out)
{
    extern __shared__ char smem[];
    uint2*  W1q  = (uint2*)(smem + OFF_W1);
    uint2*  W2q  = (uint2*)(smem + OFF_W2);
    float*  szs  = (float*)(smem + OFF_SZS);
    float*  szsh = (float*)(smem + OFF_SZSH);
    float2* sB1  = (float2*)(smem + OFF_B1);
    float2* sG1w = (float2*)(smem + OFF_G1W);
    float2* sG1b = (float2*)(smem + OFF_G1B);
    float2* sB2  = (float2*)(smem + OFF_B2);
    float2* sG2w = (float2*)(smem + OFF_G2W);
    float2* sG2b = (float2*)(smem + OFF_G2B);
    float4* sW3  = (float4*)(smem + OFF_W3);

    const int tid = threadIdx.x;
    const int wid = tid >> 5;
    const int lane = tid & 31;
    const int gid = lane >> 2;
    const int t4 = lane & 3;

    const int start = (int)(((long long)blockIdx.x * NITEMS) / GRID_MAIN);
    const int end   = (int)(((long long)(blockIdx.x + 1) * NITEMS) / GRID_MAIN);

    int cur_l = -1;
    float b3_0 = 0.f, b3_1 = 0.f, sc0 = 1.f, sc1 = 1.f, isc0 = 1.f, isc1 = 1.f;

    for (int item = start; item < end; item++) {
        const int l = item >> 6;
        const int tile = item & 63;

        if (l != cur_l) {
            __syncthreads();
            const float* W1g = W1 + l * C_ * 104;
            for (int idx = tid; idx < 128 * 28; idx += 256) {
                int c = idx / 28, q = idx - c * 28;
                int kk = q >> 2, tq = q & 3;
                int d0 = kk * 16 + tq * 2, d1 = d0 + 8;
                float w00 = W1g[c * 104 + d0];
                float w01 = W1g[c * 104 + d0 + 1];
                float w10 = (d1     < 104) ? W1g[c * 104 + d1]     : 0.0f;
                float w11 = (d1 + 1 < 104) ? W1g[c * 104 + d1 + 1] : 0.0f;
                W1q[c * 28 + q] = make_uint2(pack2h(w00, w01), pack2h(w10, w11));
            }
            const float* W2g = W2 + l * C_ * C_;
            for (int idx = tid; idx < 128 * 32; idx += 256) {
                int c = idx >> 5, q = idx & 31;
                int kk = q >> 2, tq = q & 3;
                int d0 = kk * 16 + tq * 2, d1 = d0 + 8;
                W2q[c * 36 + q] = make_uint2(
                    pack2h(W2g[c * C_ + d0], W2g[c * C_ + d0 + 1]),
                    pack2h(W2g[c * C_ + d1], W2g[c * C_ + d1 + 1]));
            }
            if (tid < 64) {
                sB1[tid]  = ((const float2*)(b1g  + l * C_))[tid];
                sG1w[tid] = ((const float2*)(g1wg + l * C_))[tid];
                sG1b[tid] = ((const float2*)(g1bg + l * C_))[tid];
                sB2[tid]  = ((const float2*)(b2g  + l * C_))[tid];
                sG2w[tid] = ((const float2*)(g2wg + l * C_))[tid];
                sG2b[tid] = ((const float2*)(g2bg + l * C_))[tid];
                int c0 = 2 * tid;
                sW3[tid] = make_float4(W3g[l * 2 * C_ + c0], W3g[l * 2 * C_ + C_ + c0],
                                       W3g[l * 2 * C_ + c0 + 1], W3g[l * 2 * C_ + C_ + c0 + 1]);
            }
            b3_0 = b3g[l * 2]; b3_1 = b3g[l * 2 + 1];
            sc0 = __expf(tsc[l * 2]); sc1 = __expf(tsc[l * 2 + 1]);
            isc0 = 1.0f / sc0; isc1 = 1.0f / sc1;
            __syncthreads();
            cur_l = l;
        }

        // stage z rows for this tile (16 b's)
        __syncthreads();
        for (int idx = tid; idx < 512; idx += 256) {
            szs[idx]  = z_sample[tile * 16 * L_ + idx];
            szsh[idx] = z_shared[tile * 16 * S_ + idx];
        }
        __syncthreads();

        // per-thread rows: r0 = wid*16+gid, r1 = r0+8
        const int grow0 = tile * 128 + wid * 16 + gid;
        const int grow1 = grow0 + 8;
        const int b0i = grow0 >> 3, b1i = grow1 >> 3;
        const unsigned Mw0 = g_mask[grow0 * L_ + l];
        const unsigned Mw1 = g_mask[grow1 * L_ + l];
        const int tgt0 = target[b0i], tgt1 = target[b1i];
        const bool tf0 = (g_ci[b0i * L_ + l] == tgt0);
        const bool tf1 = (g_ci[b1i * L_ + l] == tgt1);
        const float* zr0 = szs  + (2 * wid) * 32;
        const float* zr1 = zr0 + 32;
        const float* zh0 = szsh + (2 * wid) * 32;
        const float* zh1 = zh0 + 32;

        // ---- build A1 fragments (fp16) ----
        unsigned Ah[7][4];
#pragma unroll
        for (int kk = 0; kk < 7; kk++) {
            int db = kk * 16 + t4 * 2;
            Ah[kk][0] = pack2h(xval(db,     Mw0, tf0, tgt0, zr0, zh0),
                               xval(db + 1, Mw0, tf0, tgt0, zr0, zh0));
            Ah[kk][1] = pack2h(xval(db,     Mw1, tf1, tgt1, zr1, zh1),
                               xval(db + 1, Mw1, tf1, tgt1, zr1, zh1));
            Ah[kk][2] = pack2h(xval(db + 8, Mw0, tf0, tgt0, zr0, zh0),
                               xval(db + 9, Mw0, tf0, tgt0, zr0, zh0));
            Ah[kk][3] = pack2h(xval(db + 8, Mw1, tf1, tgt1, zr1, zh1),
                               xval(db + 9, Mw1, tf1, tgt1, zr1, zh1));
        }

        // ---- MMA1 ----
        float acc[16][4];
#pragma unroll
        for (int nt = 0; nt < 16; nt++)
#pragma unroll
            for (int i = 0; i < 4; i++) acc[nt][i] = 0.0f;

#pragma unroll
        for (int nt = 0; nt < 16; nt++) {
            const uint2* bp = W1q + (nt * 8 + gid) * 28 + t4;
#pragma unroll
            for (int kk = 0; kk < 7; kk++) {
                uint2 bq = bp[kk * 4];
                mma_f16(acc[nt], Ah[kk][0], Ah[kk][1], Ah[kk][2], Ah[kk][3], bq.x, bq.y);
            }
        }

        // ---- GN1 + SiLU -> A2 fragments ----
        float s0 = 0.f, q0 = 0.f, s1 = 0.f, q1 = 0.f;
#pragma unroll
        for (int nt = 0; nt < 16; nt++) {
            float2 bb = sB1[nt * 4 + t4];
            acc[nt][0] += bb.x; acc[nt][1] += bb.y;
            acc[nt][2] += bb.x; acc[nt][3] += bb.y;
            s0 += acc[nt][0] + acc[nt][1];
            q0 += acc[nt][0] * acc[nt][0] + acc[nt][1] * acc[nt][1];
            s1 += acc[nt][2] + acc[nt][3];
            q1 += acc[nt][2] * acc[nt][2] + acc[nt][3] * acc[nt][3];
        }
#pragma unroll
        for (int o = 1; o <= 2; o <<= 1) {
            s0 += __shfl_xor_sync(0xffffffffu, s0, o);
            q0 += __shfl_xor_sync(0xffffffffu, q0, o);
            s1 += __shfl_xor_sync(0xffffffffu, s1, o);
            q1 += __shfl_xor_sync(0xffffffffu, q1, o);
        }
        float mu0 = s0 * (1.0f / 128.0f);
        float inv0 = rsqrtf(q0 * (1.0f / 128.0f) - mu0 * mu0 + 1e-5f);
        float mu1 = s1 * (1.0f / 128.0f);
        float inv1 = rsqrtf(q1 * (1.0f / 128.0f) - mu1 * mu1 + 1e-5f);

        unsigned A2h[8][4];
#pragma unroll
        for (int kk = 0; kk < 8; kk++) {
            int nt0 = 2 * kk, nt1 = 2 * kk + 1;
            float2 w0 = sG1w[nt0 * 4 + t4], c0v = sG1b[nt0 * 4 + t4];
            float2 w1 = sG1w[nt1 * 4 + t4], c1v = sG1b[nt1 * 4 + t4];
            float h00 = silu_f((acc[nt0][0] - mu0) * inv0 * w0.x + c0v.x);
            float h01 = silu_f((acc[nt0][1] - mu0) * inv0 * w0.y + c0v.y);
            float h02 = silu_f((acc[nt0][2] - mu1) * inv1 * w0.x + c0v.x);
            float h03 = silu_f((acc[nt0][3] - mu1) * inv1 * w0.y + c0v.y);
            float h10 = silu_f((acc[nt1][0] - mu0) * inv0 * w1.x + c1v.x);
            float h11 = silu_f((acc[nt1][1] - mu0) * inv0 * w1.y + c1v.y);
            float h12 = silu_f((acc[nt1][2] - mu1) * inv1 * w1.x + c1v.x);
            float h13 = silu_f((acc[nt1][3] - mu1) * inv1 * w1.y + c1v.y);
            A2h[kk][0] = pack2h(h00, h01);
            A2h[kk][1] = pack2h(h02, h03);
            A2h[kk][2] = pack2h(h10, h11);
            A2h[kk][3] = pack2h(h12, h13);
        }

        // ---- MMA2 ----
#pragma unroll
        for (int nt = 0; nt < 16; nt++)
#pragma unroll
            for (int i = 0; i < 4; i++) acc[nt][i] = 0.0f;

#pragma unroll
        for (int nt = 0; nt < 16; nt++) {
            const uint2* bp = W2q + (nt * 8 + gid) * 36 + t4;
#pragma unroll
            for (int kk = 0; kk < 8; kk++) {
                uint2 bq = bp[kk * 4];
                mma_f16(acc[nt], A2h[kk][0], A2h[kk][1], A2h[kk][2], A2h[kk][3], bq.x, bq.y);
            }
        }

        // ---- GN2 + SiLU + layer3 + KL ----
        s0 = 0.f; q0 = 0.f; s1 = 0.f; q1 = 0.f;
#pragma unroll
        for (int nt = 0; nt < 16; nt++) {
            float2 bb = sB2[nt * 4 + t4];
            acc[nt][0] += bb.x; acc[nt][1] += bb.y;
            acc[nt][2] += bb.x; acc[nt][3] += bb.y;
            s0 += acc[nt][0] + acc[nt][1];
            q0 += acc[nt][0] * acc[nt][0] + acc[nt][1] * acc[nt][1];
            s1 += acc[nt][2] + acc[nt][3];
            q1 += acc[nt][2] * acc[nt][2] + acc[nt][3] * acc[nt][3];
        }
#pragma unroll
        for (int o = 1; o <= 2; o <<= 1) {
            s0 += __shfl_xor_sync(0xffffffffu, s0, o);
            q0 += __shfl_xor_sync(0xffffffffu, q0, o);
            s1 += __shfl_xor_sync(0xffffffffu, s1, o);
            q1 += __shfl_xor_sync(0xffffffffu, q1, o);
        }
        mu0 = s0 * (1.0f / 128.0f);
        inv0 = rsqrtf(q0 * (1.0f / 128.0f) - mu0 * mu0 + 1e-5f);
        mu1 = s1 * (1.0f / 128.0f);
        inv1 = rsqrtf(q1 * (1.0f / 128.0f) - mu1 * mu1 + 1e-5f);

        float p00 = 0.f, p10 = 0.f, p01 = 0.f, p11 = 0.f;
#pragma unroll
        for (int nt = 0; nt < 16; nt++) {
            float2 wv = sG2w[nt * 4 + t4], bv = sG2b[nt * 4 + t4];
            float4 w3 = sW3[nt * 4 + t4];
            float h0 = silu_f((acc[nt][0] - mu0) * inv0 * wv.x + bv.x);
            float h1 = silu_f((acc[nt][1] - mu0) * inv0 * wv.y + bv.y);
            float h2 = silu_f((acc[nt][2] - mu1) * inv1 * wv.x + bv.x);
            float h3 = silu_f((acc[nt][3] - mu1) * inv1 * wv.y + bv.y);
            p00 += h0 * w3.x + h1 * w3.z;
            p10 += h0 * w3.y + h1 * w3.w;
            p01 += h2 * w3.x + h3 * w3.z;
            p11 += h2 * w3.y + h3 * w3.w;
        }
#pragma unroll
        for (int o = 1; o <= 2; o <<= 1) {
            p00 += __shfl_xor_sync(0xffffffffu, p00, o);
            p10 += __shfl_xor_sync(0xffffffffu, p10, o);
            p01 += __shfl_xor_sync(0xffffffffu, p01, o);
            p11 += __shfl_xor_sync(0xffffffffu, p11, o);
        }
        if (t4 == 0) {
            {
                float o0 = p00 + b3_0, o1 = p10 + b3_1;
                float pm = tanhf(o0 * isc0) * sc0;
                float pl = tanhf(o1 * isc1) * sc1;
                float zl = z_logstd[b0i * L_ + l], zmn = z_mean[b0i * L_ + l];
                float dmu = zmn - pm;
                float kld = pl - zl + (__expf(2.0f * zl) + dmu * dmu) * 0.5f * __expf(-2.0f * pl) - 0.5f;
                atomicAdd(out + b0i, kld * 0.125f);
            }
            {
                float o0 = p01 + b3_0, o1 = p11 + b3_1;
                float pm = tanhf(o0 * isc0) * sc0;
                float pl = tanhf(o1 * isc1) * sc1;
                float zl = z_logstd[b1i * L_ + l], zmn = z_mean[b1i * L_ + l];
                float dmu = zmn - pm;
                float kld = pl - zl + (__expf(2.0f * zl) + dmu * dmu) * 0.5f * __expf(-2.0f * pl) - 0.5f;
                atomicAdd(out + b1i, kld * 0.125f);
            }
        }
    }
}

extern "C" void kernel_launch(void* const* d_in, const int* in_sizes, int n_in,
                              void* d_out, int out_size) {
    const float* z_sample      = (const float*)d_in[0];
    const int*   target        = (const int*)  d_in[1];
    const float* z_mean        = (const float*)d_in[2];
    const float* z_logstd      = (const float*)d_in[3];
    const float* z_shared      = (const float*)d_in[4];
    const float* u_gumbel      = (const float*)d_in[5];
    const float* u_adj         = (const float*)d_in[6];
    const float* target_params = (const float*)d_in[7];
    const float* enco_theta    = (const float*)d_in[8];
    const float* enco_gamma    = (const float*)d_in[9];
    const float* W1            = (const float*)d_in[10];
    const float* b1            = (const float*)d_in[11];
    const float* gn1_w         = (const float*)d_in[12];
    const float* gn1_b         = (const float*)d_in[13];
    const float* W2            = (const float*)d_in[14];
    const float* b2            = (const float*)d_in[15];
    const float* gn2_w         = (const float*)d_in[16];
    const float* gn2_b         = (const float*)d_in[17];
    const float* W3            = (const float*)d_in[18];
    const float* b3            = (const float*)d_in[19];
    const float* tanh_scale    = (const float*)d_in[20];
    float* out = (float*)d_out;

    prep_kernel<<<B_, L_>>>(target_params, u_gumbel, enco_theta, enco_gamma, out);
    prep2_kernel<<<B_, 256>>>(u_adj);

    cudaFuncSetAttribute(main_kernel, cudaFuncAttributeMaxDynamicSharedMemorySize, SMEM_BYTES);
    main_kernel<<<GRID_MAIN, 256, SMEM_BYTES>>>(
        z_sample, target, z_mean, z_logstd, z_shared,
        W1, b1, gn1_w, gn1_b, W2, b2, gn2_w, gn2_b, W3, b3, tanh_scale, out);
}

// round 7
// speedup vs baseline: 8.0727x; 1.5212x over previous
#include <cuda_runtime.h>
#include <cuda_fp16.h>
#include <math.h>

#define B_   1024
#define L_   32
#define K_   8
#define G_   8
#define C_   128
#define S_   32
#define GRID_MAIN 296
#define NTILES 64
#define NITEMS (L_ * NTILES)

__device__ unsigned char g_ci[B_ * L_];
__device__ unsigned int g_mask[B_ * G_ * L_];

// ---------- helpers ----------
__device__ __forceinline__ unsigned pack2h(float lo, float hi) {
    unsigned r;
    asm("cvt.rn.f16x2.f32 %0, %1, %2;" : "=r"(r) : "f"(hi), "f"(lo));
    return r;
}
__device__ __forceinline__ float silu_f(float x) {
    float h = 0.5f * x, t;
    asm("tanh.approx.f32 %0, %1;" : "=f"(t) : "f"(h));
    return fmaf(h, t, h);
}
__device__ __forceinline__ void mma_f16(float* c,
    unsigned a0, unsigned a1, unsigned a2, unsigned a3, unsigned b0, unsigned b1) {
    asm("mma.sync.aligned.m16n8k16.row.col.f32.f16.f16.f32 "
        "{%0,%1,%2,%3},{%4,%5,%6,%7},{%8,%9},{%0,%1,%2,%3};"
        : "+f"(c[0]), "+f"(c[1]), "+f"(c[2]), "+f"(c[3])
        : "r"(a0), "r"(a1), "r"(a2), "r"(a3), "r"(b0), "r"(b1));
}
__device__ __forceinline__ float xval(int d, unsigned Mw, bool tfl, int tgt,
                                      const float* zr, const float* zh) {
    if (d < 32)  return ((Mw >> d) & 1u) ? zr[d] : 0.0f;
    if (d < 64)  return (float)((Mw >> (d - 32)) & 1u);
    if (d < 72)  return (tfl && (d - 64) == tgt) ? 1.0f : 0.0f;
    if (d < 104) return zh[d - 72];
    return 0.0f;
}

// ---------- merged prep: ci + edge probs + masks + out zero ----------
__global__ void prep_kernel(const float* __restrict__ tp, const float* __restrict__ ug,
                            const float* __restrict__ th, const float* __restrict__ ga,
                            const float* __restrict__ u_adj, float* __restrict__ out) {
    __shared__ unsigned char sc[L_];
    __shared__ float sep[K_ * K_];
    int b = blockIdx.x, t = threadIdx.x;
    if (t < L_) {
        const float* u = ug + (b * L_ + t) * K_;
        float best = -1e30f; int bi = 0;
#pragma unroll
        for (int k = 0; k < K_; k++) {
            float gum = -logf(-logf(u[k] + 1e-10f) + 1e-10f);
            float v = tp[t * K_ + k] + gum;
            if (v > best) { best = v; bi = k; }
        }
        sc[t] = (unsigned char)bi;
        g_ci[b * L_ + t] = (unsigned char)bi;
    } else if (t >= 64 && t < 128) {
        int e = t - 64;
        float s1 = 1.0f / (1.0f + expf(-th[e]));
        float s2 = 1.0f / (1.0f + expf(-ga[e]));
        sep[e] = s1 * s2;
    }
    if (t == 0) out[b] = 0.0f;
    __syncthreads();
    int g = t >> 5, l = t & 31;
    int cl = sc[l];
    unsigned bits = 0;
#pragma unroll
    for (int cj = 0; cj < K_; cj++) {
        float u = u_adj[((b * G_ + g) * K_ + cj) * K_ + cl];
        bits |= (u < sep[cj * K_ + cl]) ? (1u << cj) : 0u;
    }
    unsigned wv = 0;
#pragma unroll
    for (int j = 0; j < L_; j++) {
        unsigned mj = (bits >> sc[j]) & 1u;
        if (j == l) mj = 0;
        wv |= mj << j;
    }
    g_mask[(b * G_ + g) * L_ + l] = wv;
}

// ---------- smem layout (bytes) ----------
// W1/W2: 128 rows x 320B (row = 4 j-groups x 4 t4 x 16B, stride 320 == 64 mod 128 -> conflict-free LDS.128)
#define OFF_W1   0
#define OFF_W2   40960
#define OFF_SZS  81920
#define OFF_SZSH 83968
#define OFF_B1   86016
#define OFF_G1W  86528
#define OFF_G1B  87040
#define OFF_B2   87552
#define OFF_G2W  88064
#define OFF_G2B  88576
#define OFF_W3   89088
#define SMEM_BYTES 90112

__global__ __launch_bounds__(256, 2) void main_kernel(
    const float* __restrict__ z_sample, const int* __restrict__ target,
    const float* __restrict__ z_mean,   const float* __restrict__ z_logstd,
    const float* __restrict__ z_shared,
    const float* __restrict__ W1, const float* __restrict__ b1g,
    const float* __restrict__ g1wg, const float* __restrict__ g1bg,
    const float* __restrict__ W2, const float* __restrict__ b2g,
    const float* __restrict__ g2wg, const float* __restrict__ g2bg,
    const float* __restrict__ W3g, const float* __restrict__ b3g,
    const float* __restrict__ tsc, float* __restrict__ out)
{
    extern __shared__ char smem[];
    uint2*  W1u2 = (uint2*)(smem + OFF_W1);
    uint2*  W2u2 = (uint2*)(smem + OFF_W2);
    const uint4* W1q4 = (const uint4*)(smem + OFF_W1);
    const uint4* W2q4 = (const uint4*)(smem + OFF_W2);
    float*  szs  = (float*)(smem + OFF_SZS);
    float*  szsh = (float*)(smem + OFF_SZSH);
    float2* sB1  = (float2*)(smem + OFF_B1);
    float2* sG1w = (float2*)(smem + OFF_G1W);
    float2* sG1b = (float2*)(smem + OFF_G1B);
    float2* sB2  = (float2*)(smem + OFF_B2);
    float2* sG2w = (float2*)(smem + OFF_G2W);
    float2* sG2b = (float2*)(smem + OFF_G2B);
    float4* sW3  = (float4*)(smem + OFF_W3);

    const int tid = threadIdx.x;
    const int wid = tid >> 5;
    const int lane = tid & 31;
    const int gid = lane >> 2;
    const int t4 = lane & 3;

    const int start = (int)(((long long)blockIdx.x * NITEMS) / GRID_MAIN);
    const int end   = (int)(((long long)(blockIdx.x + 1) * NITEMS) / GRID_MAIN);

    int cur_l = -1;
    float b3_0 = 0.f, b3_1 = 0.f, sc0 = 1.f, sc1 = 1.f, isc0 = 1.f, isc1 = 1.f;

    for (int item = start; item < end; item++) {
        const int l = item >> 6;
        const int tile = item & 63;

        if (l != cur_l) {
            __syncthreads();
            // W1: per (c, kk, tq) one uint2 {pack(d0,d0+1), pack(d1,d1+1)}
            // uint2 index = c*40 + (kk>>1)*8 + tq*2 + (kk&1)
            const float* W1g = W1 + l * C_ * 104;
            for (int idx = tid; idx < 128 * 32; idx += 256) {
                int c = idx >> 5, s = idx & 31;
                int kk = s >> 2, tq = s & 3;
                int d0 = kk * 16 + tq * 2, d1 = d0 + 8;
                float w00 = (d0     < 104) ? W1g[c * 104 + d0]     : 0.0f;
                float w01 = (d0 + 1 < 104) ? W1g[c * 104 + d0 + 1] : 0.0f;
                float w10 = (d1     < 104) ? W1g[c * 104 + d1]     : 0.0f;
                float w11 = (d1 + 1 < 104) ? W1g[c * 104 + d1 + 1] : 0.0f;
                W1u2[c * 40 + (kk >> 1) * 8 + tq * 2 + (kk & 1)] =
                    make_uint2(pack2h(w00, w01), pack2h(w10, w11));
            }
            const float* W2g = W2 + l * C_ * C_;
            for (int idx = tid; idx < 128 * 32; idx += 256) {
                int c = idx >> 5, s = idx & 31;
                int kk = s >> 2, tq = s & 3;
                int d0 = kk * 16 + tq * 2, d1 = d0 + 8;
                W2u2[c * 40 + (kk >> 1) * 8 + tq * 2 + (kk & 1)] =
                    make_uint2(pack2h(W2g[c * C_ + d0], W2g[c * C_ + d0 + 1]),
                               pack2h(W2g[c * C_ + d1], W2g[c * C_ + d1 + 1]));
            }
            if (tid < 64) {
                sB1[tid]  = ((const float2*)(b1g  + l * C_))[tid];
                sG1w[tid] = ((const float2*)(g1wg + l * C_))[tid];
                sG1b[tid] = ((const float2*)(g1bg + l * C_))[tid];
                sB2[tid]  = ((const float2*)(b2g  + l * C_))[tid];
                sG2w[tid] = ((const float2*)(g2wg + l * C_))[tid];
                sG2b[tid] = ((const float2*)(g2bg + l * C_))[tid];
                int c0 = 2 * tid;
                sW3[tid] = make_float4(W3g[l * 2 * C_ + c0], W3g[l * 2 * C_ + C_ + c0],
                                       W3g[l * 2 * C_ + c0 + 1], W3g[l * 2 * C_ + C_ + c0 + 1]);
            }
            b3_0 = b3g[l * 2]; b3_1 = b3g[l * 2 + 1];
            sc0 = __expf(tsc[l * 2]); sc1 = __expf(tsc[l * 2 + 1]);
            isc0 = 1.0f / sc0; isc1 = 1.0f / sc1;
            __syncthreads();
            cur_l = l;
        }

        // stage z rows for this tile (16 b's)
        __syncthreads();
        for (int idx = tid; idx < 512; idx += 256) {
            szs[idx]  = z_sample[tile * 16 * L_ + idx];
            szsh[idx] = z_shared[tile * 16 * S_ + idx];
        }
        __syncthreads();

        // per-thread rows: r0 = wid*16+gid, r1 = r0+8
        const int grow0 = tile * 128 + wid * 16 + gid;
        const int grow1 = grow0 + 8;
        const int b0i = grow0 >> 3, b1i = grow1 >> 3;
        const unsigned Mw0 = g_mask[grow0 * L_ + l];
        const unsigned Mw1 = g_mask[grow1 * L_ + l];
        const int tgt0 = target[b0i], tgt1 = target[b1i];
        const bool tf0 = (g_ci[b0i * L_ + l] == tgt0);
        const bool tf1 = (g_ci[b1i * L_ + l] == tgt1);
        const float* zr0 = szs  + (2 * wid) * 32;
        const float* zr1 = zr0 + 32;
        const float* zh0 = szsh + (2 * wid) * 32;
        const float* zh1 = zh0 + 32;

        // ---- build A1 fragments (fp16) ----
        unsigned Ah[7][4];
#pragma unroll
        for (int kk = 0; kk < 7; kk++) {
            int db = kk * 16 + t4 * 2;
            Ah[kk][0] = pack2h(xval(db,     Mw0, tf0, tgt0, zr0, zh0),
                               xval(db + 1, Mw0, tf0, tgt0, zr0, zh0));
            Ah[kk][1] = pack2h(xval(db,     Mw1, tf1, tgt1, zr1, zh1),
                               xval(db + 1, Mw1, tf1, tgt1, zr1, zh1));
            Ah[kk][2] = pack2h(xval(db + 8, Mw0, tf0, tgt0, zr0, zh0),
                               xval(db + 9, Mw0, tf0, tgt0, zr0, zh0));
            Ah[kk][3] = pack2h(xval(db + 8, Mw1, tf1, tgt1, zr1, zh1),
                               xval(db + 9, Mw1, tf1, tgt1, zr1, zh1));
        }

        // ---- MMA1 ----
        float acc[16][4];
#pragma unroll
        for (int nt = 0; nt < 16; nt++)
#pragma unroll
            for (int i = 0; i < 4; i++) acc[nt][i] = 0.0f;

#pragma unroll
        for (int nt = 0; nt < 16; nt++) {
            const uint4* bp = W1q4 + (nt * 8 + gid) * 20 + t4;
#pragma unroll
            for (int j = 0; j < 4; j++) {
                uint4 bq = bp[j * 4];
                mma_f16(acc[nt], Ah[2*j][0], Ah[2*j][1], Ah[2*j][2], Ah[2*j][3], bq.x, bq.y);
                if (j < 3)
                    mma_f16(acc[nt], Ah[2*j+1][0], Ah[2*j+1][1], Ah[2*j+1][2], Ah[2*j+1][3], bq.z, bq.w);
            }
        }

        // ---- GN1 + SiLU -> A2 fragments ----
        float s0 = 0.f, q0 = 0.f, s1 = 0.f, q1 = 0.f;
#pragma unroll
        for (int nt = 0; nt < 16; nt++) {
            float2 bb = sB1[nt * 4 + t4];
            acc[nt][0] += bb.x; acc[nt][1] += bb.y;
            acc[nt][2] += bb.x; acc[nt][3] += bb.y;
            s0 += acc[nt][0] + acc[nt][1];
            q0 += acc[nt][0] * acc[nt][0] + acc[nt][1] * acc[nt][1];
            s1 += acc[nt][2] + acc[nt][3];
            q1 += acc[nt][2] * acc[nt][2] + acc[nt][3] * acc[nt][3];
        }
#pragma unroll
        for (int o = 1; o <= 2; o <<= 1) {
            s0 += __shfl_xor_sync(0xffffffffu, s0, o);
            q0 += __shfl_xor_sync(0xffffffffu, q0, o);
            s1 += __shfl_xor_sync(0xffffffffu, s1, o);
            q1 += __shfl_xor_sync(0xffffffffu, q1, o);
        }
        float mu0 = s0 * (1.0f / 128.0f);
        float inv0 = rsqrtf(q0 * (1.0f / 128.0f) - mu0 * mu0 + 1e-5f);
        float mu1 = s1 * (1.0f / 128.0f);
        float inv1 = rsqrtf(q1 * (1.0f / 128.0f) - mu1 * mu1 + 1e-5f);

        unsigned A2h[8][4];
#pragma unroll
        for (int kk = 0; kk < 8; kk++) {
            int nt0 = 2 * kk, nt1 = 2 * kk + 1;
            float2 w0 = sG1w[nt0 * 4 + t4], c0v = sG1b[nt0 * 4 + t4];
            float2 w1 = sG1w[nt1 * 4 + t4], c1v = sG1b[nt1 * 4 + t4];
            float h00 = silu_f((acc[nt0][0] - mu0) * inv0 * w0.x + c0v.x);
            float h01 = silu_f((acc[nt0][1] - mu0) * inv0 * w0.y + c0v.y);
            float h02 = silu_f((acc[nt0][2] - mu1) * inv1 * w0.x + c0v.x);
            float h03 = silu_f((acc[nt0][3] - mu1) * inv1 * w0.y + c0v.y);
            float h10 = silu_f((acc[nt1][0] - mu0) * inv0 * w1.x + c1v.x);
            float h11 = silu_f((acc[nt1][1] - mu0) * inv0 * w1.y + c1v.y);
            float h12 = silu_f((acc[nt1][2] - mu1) * inv1 * w1.x + c1v.x);
            float h13 = silu_f((acc[nt1][3] - mu1) * inv1 * w1.y + c1v.y);
            A2h[kk][0] = pack2h(h00, h01);
            A2h[kk][1] = pack2h(h02, h03);
            A2h[kk][2] = pack2h(h10, h11);
            A2h[kk][3] = pack2h(h12, h13);
        }

        // ---- MMA2 ----
#pragma unroll
        for (int nt = 0; nt < 16; nt++)
#pragma unroll
            for (int i = 0; i < 4; i++) acc[nt][i] = 0.0f;

#pragma unroll
        for (int nt = 0; nt < 16; nt++) {
            const uint4* bp = W2q4 + (nt * 8 + gid) * 20 + t4;
#pragma unroll
            for (int j = 0; j < 4; j++) {
                uint4 bq = bp[j * 4];
                mma_f16(acc[nt], A2h[2*j][0], A2h[2*j][1], A2h[2*j][2], A2h[2*j][3], bq.x, bq.y);
                mma_f16(acc[nt], A2h[2*j+1][0], A2h[2*j+1][1], A2h[2*j+1][2], A2h[2*j+1][3], bq.z, bq.w);
            }
        }

        // ---- GN2 + SiLU + layer3 + KL ----
        s0 = 0.f; q0 = 0.f; s1 = 0.f; q1 = 0.f;
#pragma unroll
        for (int nt = 0; nt < 16; nt++) {
            float2 bb = sB2[nt * 4 + t4];
            acc[nt][0] += bb.x; acc[nt][1] += bb.y;
            acc[nt][2] += bb.x; acc[nt][3] += bb.y;
            s0 += acc[nt][0] + acc[nt][1];
            q0 += acc[nt][0] * acc[nt][0] + acc[nt][1] * acc[nt][1];
            s1 += acc[nt][2] + acc[nt][3];
            q1 += acc[nt][2] * acc[nt][2] + acc[nt][3] * acc[nt][3];
        }
#pragma unroll
        for (int o = 1; o <= 2; o <<= 1) {
            s0 += __shfl_xor_sync(0xffffffffu, s0, o);
            q0 += __shfl_xor_sync(0xffffffffu, q0, o);
            s1 += __shfl_xor_sync(0xffffffffu, s1, o);
            q1 += __shfl_xor_sync(0xffffffffu, q1, o);
        }
        mu0 = s0 * (1.0f / 128.0f);
        inv0 = rsqrtf(q0 * (1.0f / 128.0f) - mu0 * mu0 + 1e-5f);
        mu1 = s1 * (1.0f / 128.0f);
        inv1 = rsqrtf(q1 * (1.0f / 128.0f) - mu1 * mu1 + 1e-5f);

        float p00 = 0.f, p10 = 0.f, p01 = 0.f, p11 = 0.f;
#pragma unroll
        for (int nt = 0; nt < 16; nt++) {
            float2 wv = sG2w[nt * 4 + t4], bv = sG2b[nt * 4 + t4];
            float4 w3 = sW3[nt * 4 + t4];
            float h0 = silu_f((acc[nt][0] - mu0) * inv0 * wv.x + bv.x);
            float h1 = silu_f((acc[nt][1] - mu0) * inv0 * wv.y + bv.y);
            float h2 = silu_f((acc[nt][2] - mu1) * inv1 * wv.x + bv.x);
            float h3 = silu_f((acc[nt][3] - mu1) * inv1 * wv.y + bv.y);
            p00 += h0 * w3.x + h1 * w3.z;
            p10 += h0 * w3.y + h1 * w3.w;
            p01 += h2 * w3.x + h3 * w3.z;
            p11 += h2 * w3.y + h3 * w3.w;
        }
#pragma unroll
        for (int o = 1; o <= 2; o <<= 1) {
            p00 += __shfl_xor_sync(0xffffffffu, p00, o);
            p10 += __shfl_xor_sync(0xffffffffu, p10, o);
            p01 += __shfl_xor_sync(0xffffffffu, p01, o);
            p11 += __shfl_xor_sync(0xffffffffu, p11, o);
        }
        if (t4 == 0) {
            {
                float o0 = p00 + b3_0, o1 = p10 + b3_1;
                float pm = tanhf(o0 * isc0) * sc0;
                float pl = tanhf(o1 * isc1) * sc1;
                float zl = z_logstd[b0i * L_ + l], zmn = z_mean[b0i * L_ + l];
                float dmu = zmn - pm;
                float kld = pl - zl + (__expf(2.0f * zl) + dmu * dmu) * 0.5f * __expf(-2.0f * pl) - 0.5f;
                atomicAdd(out + b0i, kld * 0.125f);
            }
            {
                float o0 = p01 + b3_0, o1 = p11 + b3_1;
                float pm = tanhf(o0 * isc0) * sc0;
                float pl = tanhf(o1 * isc1) * sc1;
                float zl = z_logstd[b1i * L_ + l], zmn = z_mean[b1i * L_ + l];
                float dmu = zmn - pm;
                float kld = pl - zl + (__expf(2.0f * zl) + dmu * dmu) * 0.5f * __expf(-2.0f * pl) - 0.5f;
                atomicAdd(out + b1i, kld * 0.125f);
            }
        }
    }
}

extern "C" void kernel_launch(void* const* d_in, const int* in_sizes, int n_in,
                              void* d_out, int out_size) {
    const float* z_sample      = (const float*)d_in[0];
    const int*   target        = (const int*)  d_in[1];
    const float* z_mean        = (const float*)d_in[2];
    const float* z_logstd      = (const float*)d_in[3];
    const float* z_shared      = (const float*)d_in[4];
    const float* u_gumbel      = (const float*)d_in[5];
    const float* u_adj         = (const float*)d_in[6];
    const float* target_params = (const float*)d_in[7];
    const float* enco_theta    = (const float*)d_in[8];
    const float* enco_gamma    = (const float*)d_in[9];
    const float* W1            = (const float*)d_in[10];
    const float* b1            = (const float*)d_in[11];
    const float* gn1_w         = (const float*)d_in[12];
    const float* gn1_b         = (const float*)d_in[13];
    const float* W2            = (const float*)d_in[14];
    const float* b2            = (const float*)d_in[15];
    const float* gn2_w         = (const float*)d_in[16];
    const float* gn2_b         = (const float*)d_in[17];
    const float* W3            = (const float*)d_in[18];
    const float* b3            = (const float*)d_in[19];
    const float* tanh_scale    = (const float*)d_in[20];
    float* out = (float*)d_out;

    prep_kernel<<<B_, 256>>>(target_params, u_gumbel, enco_theta, enco_gamma, u_adj, out);

    cudaFuncSetAttribute(main_kernel, cudaFuncAttributeMaxDynamicSharedMemorySize, SMEM_BYTES);
    main_kernel<<<GRID_MAIN, 256, SMEM_BYTES>>>(
        z_sample, target, z_mean, z_logstd, z_shared,
        W1, b1, gn1_w, gn1_b, W2, b2, gn2_w, gn2_b, W3, b3, tanh_scale, out);
}